// round 2
// baseline (speedup 1.0000x reference)
#include <cuda_runtime.h>
#include <math.h>
#include <stdint.h>

// ---------------- problem constants ----------------
#define NN 100000
#define EE 1600000
#define FD 125
#define PD 3
#define MSEL 131072            // pow2 >= NN
#define NLCAP 131072           // >= NN: neighborhood can never truncate
#define BMPW (1u<<24)          // 2^24 words = 2^30 bits bitmap (c <= 32768)
#define CMAXB 32768
#define QSCALE 17179869184.0   // 2^34 fixed-point scale
#define QINV   (1.0/17179869184.0)

// ---------------- static device scratch ----------------
__device__ double  g_sroot[NN];
__device__ double  g_srel[NN];
__device__ long long g_qrel[NN];
__device__ unsigned long long g_relfix[NN];   // two's complement fixed point sum
__device__ int     g_deg[NN];
__device__ int     g_indptr[NN + 1];
__device__ int     g_fill[NN];
__device__ int     g_adj[NN + EE];
__device__ unsigned long long g_key[MSEL];
__device__ int     g_cluster[NN];
__device__ int     g_oid[NN];
__device__ int     g_cidpos[NN];
__device__ int     g_centers[NN];
__device__ int     g_buggy[NN];
__device__ int     g_f0[NN];
__device__ int     g_f1[NN];
__device__ int     g_nlist[NLCAP];
__device__ unsigned int g_enc[NN * FD];       // 50MB
__device__ unsigned long long g_bmp[BMPW];    // 128MB
__device__ int     g_rowcnt[NN];
__device__ int     g_rowincl[NN];
__device__ int     g_aux[128];
__device__ int     g_selfcnt;
__device__ int     g_degmin;
__device__ int     g_depth;
__device__ int     g_c;
__device__ int     g_Etot;

// ---------------- init ----------------
__global__ void k_init() {
    int v = blockIdx.x * blockDim.x + threadIdx.x;
    if (v < NN) {
        g_deg[v] = 1;        // appended self-loop
        g_relfix[v] = 0ull;
        g_cluster[v] = -1;
    }
    if (v == 0) { g_selfcnt = 0; g_degmin = 0x7fffffff; }
}

// ---------------- per-node 128-dim dots (fp64, warp per node) ----------------
__global__ void k_dots(const float* __restrict__ x, const float* __restrict__ pos,
                       const float* __restrict__ wroot, const float* __restrict__ wrel) {
    int tid = threadIdx.x;
    int warp = tid >> 5, lane = tid & 31;
    int v = blockIdx.x * 8 + warp;
    if (v >= NN) return;
    double ar = 0.0, rr = 0.0;
    for (int d = lane; d < 128; d += 32) {
        double val = (d < FD) ? (double)x[(size_t)v * FD + d]
                              : (double)pos[(size_t)v * PD + (d - FD)];
        ar += val * (double)wroot[d];
        rr += val * (double)wrel[d];
    }
    for (int o = 16; o > 0; o >>= 1) {
        ar += __shfl_down_sync(0xffffffffu, ar, o);
        rr += __shfl_down_sync(0xffffffffu, rr, o);
    }
    if (lane == 0) {
        g_sroot[v] = ar;
        g_srel[v]  = rr;
        g_qrel[v]  = llrint(rr * QSCALE);
    }
}

// ---------------- edge pass: degree, selfcount, fixed-point score agg ----------------
__global__ void k_edge1(const int* __restrict__ ei) {
    int e = blockIdx.x * blockDim.x + threadIdx.x;
    if (e >= EE) return;
    int s = ei[e], d = ei[EE + e];
    if (s == d) {
        atomicAdd(&g_selfcnt, 1);
    } else {
        atomicAdd(&g_deg[s], 1);
        atomicAdd(&g_relfix[d], (unsigned long long)g_qrel[s]);
    }
}

__global__ void k_minred() {
    int v = blockIdx.x * blockDim.x + threadIdx.x;
    if (v < NN) atomicMin(&g_degmin, g_deg[v]);
}

// k = int(-(log(1/0.8) // -log(mean-min))) + 1 = ceil(a/b)+1 ; depth = k+1
__global__ void k_kcalc() {
    long long kept = (long long)EE - g_selfcnt;
    double mean = (double)(kept + NN) / (double)NN;
    double b = log(mean - (double)g_degmin);
    double a = log(1.0 / 0.8);
    long long kk = (long long)ceil(a / b);
    int d = (int)kk + 2;   // depth = k+1, k = kk+1
    if (d < 1) d = 1;
    if (d > 16) d = 16;
    g_depth = d;
}

// ---------------- score -> sortable key ----------------
__global__ void k_key(const float* __restrict__ bptr) {
    int i = blockIdx.x * blockDim.x + threadIdx.x;
    if (i >= MSEL) return;
    if (i < NN) {
        double sc = g_sroot[i] + g_srel[i] + (double)(long long)g_relfix[i] * QINV
                  + (double)bptr[0];
        float f = (float)sc;
        unsigned u = __float_as_uint(f);
        u = (u >> 31) ? ~u : (u | 0x80000000u);   // monotone ascending map
        unsigned du = ~u;                          // descending score
        g_key[i] = ((unsigned long long)du << 32) | (unsigned)i;
    } else {
        g_key[i] = ~0ull;
    }
}

__global__ void k_bitonic(int j, int k2) {
    int i = blockIdx.x * blockDim.x + threadIdx.x;
    int ixj = i ^ j;
    if (ixj > i) {
        unsigned long long a = g_key[i], b = g_key[ixj];
        bool up = ((i & k2) == 0);
        if ((a > b) == up) { g_key[i] = b; g_key[ixj] = a; }
    }
}

// ---------------- scan A: deg -> indptr ----------------
__global__ void k_scanA1() {
    __shared__ int sh[1024];
    int b = blockIdx.x, tid = threadIdx.x;
    int idx = b * 1024 + tid;
    int v = (idx < NN) ? g_deg[idx] : 0;
    sh[tid] = v;
    __syncthreads();
    for (int d = 1; d < 1024; d <<= 1) {
        int t = (tid >= d) ? sh[tid - d] : 0;
        __syncthreads();
        sh[tid] += t;
        __syncthreads();
    }
    if (idx < NN) g_indptr[idx + 1] = sh[tid];
    if (tid == 1023) g_aux[b] = sh[1023];
}
__global__ void k_scanA2() {
    int run = 0;
    for (int b = 0; b < 98; b++) { int t = g_aux[b]; g_aux[b] = run; run += t; }
    g_indptr[0] = 0;
}
__global__ void k_scanA3() {
    int idx = blockIdx.x * 1024 + threadIdx.x;
    if (idx < NN) g_indptr[idx + 1] += g_aux[idx >> 10];
}

// self-loop at slot 0 of each node's adjacency (deterministic), fill ptr after it
__global__ void k_fillself() {
    int v = blockIdx.x * 1024 + threadIdx.x;
    if (v < NN) {
        int p = g_indptr[v];
        g_adj[p] = v;
        g_fill[v] = p + 1;
    }
}
__global__ void k_adjE(const int* __restrict__ ei) {
    int e = blockIdx.x * blockDim.x + threadIdx.x;
    if (e >= EE) return;
    int s = ei[e], d = ei[EE + e];
    if (s != d) g_adj[atomicAdd(&g_fill[s], 1)] = d;
}

// ---------------- persistent greedy peel (single block, hang-proof) ----------------
__global__ void __launch_bounds__(1024, 1) k_peel() {
    __shared__ int shp, shc, shoff, shfsz, shnext, shnsz, shmin, shdepth, shstop;
    int tid = threadIdx.x;
    if (tid == 0) { shp = 0; shc = 0; shoff = 0; shdepth = g_depth; shstop = 0; }
    __syncthreads();
    for (int iter = 0; iter < NN; iter++) {
        if (shoff >= NN || shstop) break;
        // --- find next alive node in sel order (bounded window scan) ---
        if (tid == 0) shmin = 1024;
        __syncthreads();
        while (true) {
            if (shp >= NN) { if (tid == 0) shstop = 1; __syncthreads(); break; }
            int idx = shp + tid;
            int ok = 0;
            if (idx < NN) {
                int s = (int)(g_key[idx] & 0xffffffffu);
                if (s >= 0 && s < NN && g_cluster[s] == -1) ok = 1;
            }
            if (ok) atomicMin(&shmin, tid);
            __syncthreads();
            if (shmin < 1024) break;
            if (tid == 0) { shp += 1024; shmin = 1024; }
            __syncthreads();
        }
        if (shstop) break;
        if (tid == 0) {
            int pos = shp + shmin;
            int center = (int)(g_key[pos] & 0xffffffffu);
            shp = pos + 1;
            g_cluster[center] = shc;
            g_centers[shc] = center;
            g_nlist[0] = center; shnsz = 1;
            g_f0[0] = center;    shfsz = 1;
        }
        __syncthreads();
        // --- BFS expansion, depth levels (claim set is deterministic) ---
        int* fcur = g_f0; int* fnext = g_f1;
        int depth = shdepth;
        for (int step = 0; step < depth; step++) {
            if (tid == 0) shnext = 0;
            __syncthreads();
            int fsz = shfsz, cc = shc;
            for (int i = tid; i < fsz; i += 1024) {
                int u = fcur[i];
                int e0 = g_indptr[u], e1 = g_indptr[u + 1];
                for (int e = e0; e < e1; e++) {
                    int w = g_adj[e];
                    if (g_cluster[w] == -1) {
                        if (atomicCAS(&g_cluster[w], -1, cc) == -1) {
                            int j = atomicAdd(&shnext, 1);
                            fnext[j] = w;
                            int j2 = atomicAdd(&shnsz, 1);
                            g_nlist[j2] = w;     // j2 < NN <= NLCAP always
                        }
                    }
                }
            }
            __syncthreads();
            if (shnext == 0) break;
            if (tid == 0) shfsz = shnext;
            __syncthreads();
            int* t = fcur; fcur = fnext; fnext = t;
        }
        __syncthreads();
        int nsz = shnsz;
        // --- sort neighborhood ascending (reference emits each sorted) ---
        if (nsz > 1) {
            int m = 1; while (m < nsz) m <<= 1;
            for (int i = nsz + tid; i < m; i += 1024) g_nlist[i] = 0x7fffffff;
            __syncthreads();
            for (int k2 = 2; k2 <= m; k2 <<= 1) {
                for (int j = k2 >> 1; j > 0; j >>= 1) {
                    for (int i = tid; i < m; i += 1024) {
                        int ixj = i ^ j;
                        if (ixj > i) {
                            int a = g_nlist[i], b = g_nlist[ixj];
                            bool up = ((i & k2) == 0);
                            if ((a > b) == up) { g_nlist[i] = b; g_nlist[ixj] = a; }
                        }
                    }
                    __syncthreads();
                }
            }
        }
        int off = shoff, cc = shc;
        for (int i = tid; i < nsz; i += 1024) {
            int p = off + i;
            if (p < NN) { g_oid[p] = g_nlist[i]; g_cidpos[p] = cc; }
        }
        __syncthreads();
        if (tid == 0) { shoff += nsz; shc += 1; }
        __syncthreads();
    }
    if (tid == 0) g_c = shc;
}

// ---------------- buggy cluster relabeling: buggy[v] = cid[oid[v]] ----------------
__global__ void k_buggy() {
    int v = blockIdx.x * blockDim.x + threadIdx.x;
    if (v < NN) g_buggy[v] = g_cidpos[g_oid[v]];
}

// ---------------- edge dedup bitmap ----------------
__global__ void k_clearbmp() {
    int c = g_c; if (c > CMAXB) c = CMAXB;
    long long cw = (c + 63) >> 6;
    long long nw = (long long)c * cw;
    if (nw > (long long)BMPW) nw = BMPW;
    long long stride = (long long)gridDim.x * blockDim.x;
    for (long long i = blockIdx.x * (long long)blockDim.x + threadIdx.x; i < nw; i += stride)
        g_bmp[i] = 0ull;
}
__global__ void k_mark(const int* __restrict__ ei) {
    int e = blockIdx.x * blockDim.x + threadIdx.x;
    if (e >= EE) return;
    int s = ei[e], d = ei[EE + e];
    if (s == d) return;
    int a = g_buggy[s], b = g_buggy[d];
    if (a == b) return;
    int c = g_c;
    if (c > CMAXB) return;                       // safety clamp
    long long cw = (c + 63) >> 6;
    if (a < 0 || a >= c || b < 0 || b >= c) return;
    long long bit = (long long)a * (cw << 6) + b;
    atomicOr(&g_bmp[bit >> 6], 1ull << (bit & 63));
}
__global__ void k_rowcnt() {
    int a = blockIdx.x * blockDim.x + threadIdx.x;
    int c = g_c;
    if (a >= NN) return;
    if (a >= c || c > CMAXB) { if (a < NN) g_rowcnt[a] = 0; return; }
    long long cw = (c + 63) >> 6;
    int cnt = 0;
    for (long long w = 0; w < cw; w++) cnt += __popcll(g_bmp[(long long)a * cw + w]);
    g_rowcnt[a] = cnt;
}

// ---------------- scan B: rowcnt -> rowincl (inclusive) ----------------
__global__ void k_scanB1() {
    __shared__ int sh[1024];
    int n = g_c; if (n > NN) n = NN;
    int b = blockIdx.x, tid = threadIdx.x;
    int idx = b * 1024 + tid;
    int v = (idx < n) ? g_rowcnt[idx] : 0;
    sh[tid] = v;
    __syncthreads();
    for (int d = 1; d < 1024; d <<= 1) {
        int t = (tid >= d) ? sh[tid - d] : 0;
        __syncthreads();
        sh[tid] += t;
        __syncthreads();
    }
    if (idx < n) g_rowincl[idx] = sh[tid];
    if (tid == 1023) g_aux[b] = sh[1023];
}
__global__ void k_scanB2() {
    int run = 0;
    for (int b = 0; b < 98; b++) { int t = g_aux[b]; g_aux[b] = run; run += t; }
}
__global__ void k_scanB3() {
    int n = g_c; if (n > NN) n = NN;
    int idx = blockIdx.x * 1024 + threadIdx.x;
    if (idx < n) g_rowincl[idx] += g_aux[idx >> 10];
}
__global__ void k_setE() {
    int c = g_c;
    g_Etot = (c > 0 && c <= NN) ? g_rowincl[c - 1] : 0;
}

// ---------------- x_p = segment_max ----------------
__global__ void k_xclear() {
    long long i = blockIdx.x * (long long)blockDim.x + threadIdx.x;
    if (i < (long long)NN * FD) g_enc[i] = 0u;   // encoded -inf
}
__global__ void k_xmax(const float* __restrict__ x) {
    long long i = blockIdx.x * (long long)blockDim.x + threadIdx.x;
    if (i >= (long long)NN * FD) return;
    int v = (int)(i / FD), f = (int)(i % FD);
    int cl = g_cluster[v];
    if (cl < 0 || cl >= NN) return;
    unsigned u = __float_as_uint(x[i]);
    u = (u >> 31) ? ~u : (u | 0x80000000u);
    atomicMax(&g_enc[(long long)cl * FD + f], u);
}
__global__ void k_xout(float* __restrict__ out, long long osz) {
    long long i = blockIdx.x * (long long)blockDim.x + threadIdx.x;
    if (i >= (long long)g_c * FD || i >= osz) return;
    unsigned u = g_enc[i];
    unsigned bits = (u & 0x80000000u) ? (u ^ 0x80000000u) : ~u;
    out[i] = __uint_as_float(bits);
}

// ---------------- new_ei emission (sorted unique pairs) ----------------
__global__ void k_emit(float* __restrict__ out, long long osz) {
    int a = blockIdx.x * blockDim.x + threadIdx.x;
    int c = g_c;
    if (a >= c || c > CMAXB) return;
    long long cw = (c + 63) >> 6;
    int base = g_rowincl[a] - g_rowcnt[a];
    long long eoff = (long long)FD * c;
    int Et = g_Etot;
    int cnt = 0;
    for (long long w = 0; w < cw; w++) {
        unsigned long long u = g_bmp[(long long)a * cw + w];
        while (u) {
            int bpos = __ffsll((long long)u) - 1;
            int b = (int)(w * 64 + bpos);
            long long p0 = eoff + base + cnt;
            long long p1 = eoff + Et + base + cnt;
            if (p0 >= 0 && p0 < osz) out[p0] = (float)a;
            if (p1 >= 0 && p1 < osz) out[p1] = (float)b;
            cnt++;
            u &= (u - 1);
        }
    }
}

// ---------------- pos_p ----------------
__global__ void k_posout(const float* __restrict__ pos, float* __restrict__ out,
                         long long osz) {
    int i = blockIdx.x * blockDim.x + threadIdx.x;
    int c = g_c;
    if (i >= 3 * c) return;
    int j = i / 3, d = i % 3;
    int ctr = g_centers[j];
    if (ctr < 0 || ctr >= NN) return;
    long long off = (long long)FD * c + 2LL * g_Etot + i;
    if (off >= 0 && off < osz)
        out[off] = pos[(long long)ctr * 3 + d];
}

// ---------------- launch ----------------
extern "C" void kernel_launch(void* const* d_in, const int* in_sizes, int n_in,
                              void* d_out, int out_size) {
    const float* x     = (const float*)d_in[0];
    const int*   ei    = (const int*)d_in[1];
    const float* pos   = (const float*)d_in[2];
    const float* wroot = (const float*)d_in[3];
    const float* wrel  = (const float*)d_in[4];
    const float* bb    = (const float*)d_in[5];
    float* out = (float*)d_out;
    long long osz = (long long)out_size;

    k_init<<<(NN + 255) / 256, 256>>>();
    k_dots<<<(NN + 7) / 8, 256>>>(x, pos, wroot, wrel);
    k_edge1<<<(EE + 255) / 256, 256>>>(ei);
    k_minred<<<(NN + 255) / 256, 256>>>();
    k_kcalc<<<1, 1>>>();
    k_key<<<MSEL / 256, 256>>>(bb);
    for (int k2 = 2; k2 <= MSEL; k2 <<= 1)
        for (int j = k2 >> 1; j > 0; j >>= 1)
            k_bitonic<<<MSEL / 256, 256>>>(j, k2);
    k_scanA1<<<98, 1024>>>();
    k_scanA2<<<1, 1>>>();
    k_scanA3<<<98, 1024>>>();
    k_fillself<<<98, 1024>>>();
    k_adjE<<<(EE + 255) / 256, 256>>>(ei);
    k_peel<<<1, 1024>>>();
    k_clearbmp<<<2048, 256>>>();
    k_buggy<<<(NN + 255) / 256, 256>>>();
    k_mark<<<(EE + 255) / 256, 256>>>(ei);
    k_rowcnt<<<(NN + 255) / 256, 256>>>();
    k_scanB1<<<98, 1024>>>();
    k_scanB2<<<1, 1>>>();
    k_scanB3<<<98, 1024>>>();
    k_setE<<<1, 1>>>();
    k_xclear<<<(NN * FD + 255) / 256, 256>>>();
    k_xmax<<<(NN * FD + 255) / 256, 256>>>(x);
    k_xout<<<(NN * FD + 255) / 256, 256>>>(out, osz);
    k_emit<<<(NN + 255) / 256, 256>>>(out, osz);
    k_posout<<<(3 * NN + 255) / 256, 256>>>(pos, out, osz);
}

// round 5
// speedup vs baseline: 1.1194x; 1.1194x over previous
#include <cuda_runtime.h>
#include <math.h>
#include <stdint.h>

typedef unsigned long long ull;

// ---------------- problem constants ----------------
#define NN 100000
#define EE 1600000
#define FD 125
#define PD 3
#define MSEL 131072            // pow2 >= NN
#define SFC 4096               // static smem frontier capacity per buffer (32KB total)
#define BMPW (1u<<24)          // 2^24 words = 2^30 bits bitmap (c <= 32768)
#define CMAXB 32768
#define QSCALE 17179869184.0   // 2^34 fixed-point scale
#define QINV   (1.0/17179869184.0)

// ---------------- static device scratch ----------------
__device__ double  g_sroot[NN];
__device__ double  g_srel[NN];
__device__ long long g_qrel[NN];
__device__ ull     g_relfix[NN];
__device__ int     g_deg[NN];
__device__ int     g_indptr[NN + 1];
__device__ int     g_fill[NN];
__device__ int     g_adj[NN + EE];
__device__ ull     g_key[MSEL];
__device__ int     g_cluster[NN];
__device__ int     g_centers[NN];
__device__ int     g_buggy[NN];
__device__ int     g_f0[NN];           // frontier overflow
__device__ int     g_f1[NN];
__device__ unsigned int g_enc[NN * FD];
__device__ ull     g_bmp[BMPW];        // 128MB
__device__ int     g_rowcnt[NN];
__device__ int     g_rowincl[NN];
__device__ int     g_aux[128];
__device__ int     g_selfcnt;
__device__ int     g_degmin;
__device__ int     g_depth;
__device__ int     g_c;
__device__ int     g_Etot;

// ---------------- init ----------------
__global__ void k_init() {
    int v = blockIdx.x * blockDim.x + threadIdx.x;
    if (v < NN) {
        g_deg[v] = 1;        // appended self-loop
        g_relfix[v] = 0ull;
        g_cluster[v] = -1;
    }
    if (v == 0) { g_selfcnt = 0; g_degmin = 0x7fffffff; }
}

// ---------------- per-node 128-dim dots (fp64, warp per node) ----------------
__global__ void k_dots(const float* __restrict__ x, const float* __restrict__ pos,
                       const float* __restrict__ wroot, const float* __restrict__ wrel) {
    int tid = threadIdx.x;
    int warp = tid >> 5, lane = tid & 31;
    int v = blockIdx.x * 8 + warp;
    if (v >= NN) return;
    double ar = 0.0, rr = 0.0;
    for (int d = lane; d < 128; d += 32) {
        double val = (d < FD) ? (double)x[(size_t)v * FD + d]
                              : (double)pos[(size_t)v * PD + (d - FD)];
        ar += val * (double)wroot[d];
        rr += val * (double)wrel[d];
    }
    for (int o = 16; o > 0; o >>= 1) {
        ar += __shfl_down_sync(0xffffffffu, ar, o);
        rr += __shfl_down_sync(0xffffffffu, rr, o);
    }
    if (lane == 0) {
        g_sroot[v] = ar;
        g_srel[v]  = rr;
        g_qrel[v]  = llrint(rr * QSCALE);
    }
}

// ---------------- edge pass ----------------
__global__ void k_edge1(const int* __restrict__ ei) {
    int e = blockIdx.x * blockDim.x + threadIdx.x;
    if (e >= EE) return;
    int s = ei[e], d = ei[EE + e];
    if (s == d) {
        atomicAdd(&g_selfcnt, 1);
    } else {
        atomicAdd(&g_deg[s], 1);
        atomicAdd(&g_relfix[d], (ull)g_qrel[s]);
    }
}

__global__ void k_minred() {
    int v = blockIdx.x * blockDim.x + threadIdx.x;
    if (v < NN) atomicMin(&g_degmin, g_deg[v]);
}

__global__ void k_kcalc() {
    long long kept = (long long)EE - g_selfcnt;
    double mean = (double)(kept + NN) / (double)NN;
    double b = log(mean - (double)g_degmin);
    double a = log(1.0 / 0.8);
    long long kk = (long long)ceil(a / b);
    int d = (int)kk + 2;
    if (d < 1) d = 1;
    if (d > 16) d = 16;
    g_depth = d;
}

// ---------------- score -> sortable key ----------------
__global__ void k_key(const float* __restrict__ bptr) {
    int i = blockIdx.x * blockDim.x + threadIdx.x;
    if (i >= MSEL) return;
    if (i < NN) {
        double sc = g_sroot[i] + g_srel[i] + (double)(long long)g_relfix[i] * QINV
                  + (double)bptr[0];
        float f = (float)sc;
        unsigned u = __float_as_uint(f);
        u = (u >> 31) ? ~u : (u | 0x80000000u);
        unsigned du = ~u;
        g_key[i] = ((ull)du << 32) | (unsigned)i;
    } else {
        g_key[i] = ~0ull;
    }
}

// ---------------- bitonic sort: global stage + smem-fused stages ----------------
__global__ void k_bitonic(int j, int k2) {
    int i = blockIdx.x * blockDim.x + threadIdx.x;
    int ixj = i ^ j;
    if (ixj > i) {
        ull a = g_key[i], b = g_key[ixj];
        bool up = ((i & k2) == 0);
        if ((a > b) == up) { g_key[i] = b; g_key[ixj] = a; }
    }
}

// full local sort of each 2048-block: covers k2 = 2..2048 (16KB static smem)
__global__ void __launch_bounds__(1024) k_sort_local() {
    __shared__ ull sh[2048];
    int base = blockIdx.x * 2048, t = threadIdx.x;
    sh[t] = g_key[base + t];
    sh[t + 1024] = g_key[base + t + 1024];
    __syncthreads();
    for (int k2 = 2; k2 <= 2048; k2 <<= 1) {
        for (int j = k2 >> 1; j > 0; j >>= 1) {
            #pragma unroll
            for (int q = 0; q < 2; q++) {
                int i = t + q * 1024;
                int ixj = i ^ j;
                if (ixj > i) {
                    bool up = (((base + i) & k2) == 0);
                    ull a = sh[i], b = sh[ixj];
                    if ((a > b) == up) { sh[i] = b; sh[ixj] = a; }
                }
            }
            __syncthreads();
        }
    }
    g_key[base + t] = sh[t];
    g_key[base + t + 1024] = sh[t + 1024];
}

// stages j = 1024..1 of merge step k2 (>2048), in smem
__global__ void __launch_bounds__(1024) k_merge_local(int k2) {
    __shared__ ull sh[2048];
    int base = blockIdx.x * 2048, t = threadIdx.x;
    sh[t] = g_key[base + t];
    sh[t + 1024] = g_key[base + t + 1024];
    __syncthreads();
    for (int j = 1024; j > 0; j >>= 1) {
        #pragma unroll
        for (int q = 0; q < 2; q++) {
            int i = t + q * 1024;
            int ixj = i ^ j;
            if (ixj > i) {
                bool up = (((base + i) & k2) == 0);
                ull a = sh[i], b = sh[ixj];
                if ((a > b) == up) { sh[i] = b; sh[ixj] = a; }
            }
        }
        __syncthreads();
    }
    g_key[base + t] = sh[t];
    g_key[base + t + 1024] = sh[t + 1024];
}

// ---------------- scan A: deg -> indptr ----------------
__global__ void k_scanA1() {
    __shared__ int sh[1024];
    int b = blockIdx.x, tid = threadIdx.x;
    int idx = b * 1024 + tid;
    int v = (idx < NN) ? g_deg[idx] : 0;
    sh[tid] = v;
    __syncthreads();
    for (int d = 1; d < 1024; d <<= 1) {
        int t = (tid >= d) ? sh[tid - d] : 0;
        __syncthreads();
        sh[tid] += t;
        __syncthreads();
    }
    if (idx < NN) g_indptr[idx + 1] = sh[tid];
    if (tid == 1023) g_aux[b] = sh[1023];
}
__global__ void k_scanA2() {
    int run = 0;
    for (int b = 0; b < 98; b++) { int t = g_aux[b]; g_aux[b] = run; run += t; }
    g_indptr[0] = 0;
}
__global__ void k_scanA3() {
    int idx = blockIdx.x * 1024 + threadIdx.x;
    if (idx < NN) g_indptr[idx + 1] += g_aux[idx >> 10];
}

__global__ void k_fillself() {
    int v = blockIdx.x * 1024 + threadIdx.x;
    if (v < NN) {
        int p = g_indptr[v];
        g_adj[p] = v;          // self-loop at slot 0
        g_fill[v] = p + 1;
    }
}
__global__ void k_adjE(const int* __restrict__ ei) {
    int e = blockIdx.x * blockDim.x + threadIdx.x;
    if (e >= EE) return;
    int s = ei[e], d = ei[EE + e];
    if (s != d) g_adj[atomicAdd(&g_fill[s], 1)] = d;
}

// ------- persistent greedy peel: claims only, static-smem frontiers -------
__global__ void __launch_bounds__(1024, 1) k_peel() {
    __shared__ int sA[SFC];
    __shared__ int sB[SFC];
    __shared__ int shp, shc, shclaim, shfsz, shnext, shmin, shdepth, shstop;
    int tid = threadIdx.x;
    if (tid == 0) { shp = 0; shc = 0; shclaim = 0; shdepth = g_depth; shstop = 0; }
    __syncthreads();
    for (int iter = 0; iter < NN; iter++) {
        if (shclaim >= NN || shstop) break;
        // --- find next alive node in sel order (bounded window scan) ---
        if (tid == 0) shmin = 1 << 20;
        __syncthreads();
        while (true) {
            if (shp >= NN) { if (tid == 0) shstop = 1; __syncthreads(); break; }
            int idx = shp + tid;
            if (idx < NN) {
                int s = (int)(g_key[idx] & 0xffffffffu);
                if (g_cluster[s] == -1) atomicMin(&shmin, tid);
            }
            __syncthreads();
            if (shmin < (1 << 20)) break;
            if (tid == 0) shp += 1024;
            __syncthreads();
        }
        if (shstop) break;
        if (tid == 0) {
            int pos = shp + shmin;
            int center = (int)(g_key[pos] & 0xffffffffu);
            shp = pos + 1;
            g_cluster[center] = shc;
            g_centers[shc] = center;
            sA[0] = center;
            shfsz = 1;
            shclaim += 1;
        }
        __syncthreads();
        // --- BFS claims, depth levels (claim SET is deterministic) ---
        int useA = 1;
        int depth = shdepth;
        for (int step = 0; step < depth; step++) {
            if (tid == 0) shnext = 0;
            __syncthreads();
            int fsz = shfsz, cc = shc;
            for (int i = tid; i < fsz; i += 1024) {
                int u = useA ? (i < SFC ? sA[i] : g_f0[i])
                             : (i < SFC ? sB[i] : g_f1[i]);
                int e0 = g_indptr[u] + 1, e1 = g_indptr[u + 1];  // skip self slot
                for (int e = e0; e < e1; e++) {
                    int w = g_adj[e];
                    if (g_cluster[w] == -1 && atomicCAS(&g_cluster[w], -1, cc) == -1) {
                        int j = atomicAdd(&shnext, 1);
                        if (useA) { if (j < SFC) sB[j] = w; else g_f1[j] = w; }
                        else      { if (j < SFC) sA[j] = w; else g_f0[j] = w; }
                    }
                }
            }
            __syncthreads();
            int nx = shnext;
            if (nx == 0) break;
            if (tid == 0) { shfsz = nx; shclaim += nx; }
            useA ^= 1;
            __syncthreads();
        }
        if (tid == 0) shc += 1;
        __syncthreads();
    }
    if (tid == 0) g_c = shc;
}

// ---------------- concat reconstruction: key = (cluster<<32 | node) ----------------
__global__ void k_key2() {
    int i = blockIdx.x * blockDim.x + threadIdx.x;
    if (i >= MSEL) return;
    if (i < NN) {
        int cl = g_cluster[i];
        unsigned uc = (cl < 0) ? 0x7fffffffu : (unsigned)cl;
        g_key[i] = ((ull)uc << 32) | (unsigned)i;
    } else {
        g_key[i] = ~0ull;
    }
}

// After sort: position p holds key[p] = (cid[p]<<32 | oid[p]).
// Reference: clusters_buggy[v] = cid[ oid[v] ]  (cluster-id AT POSITION oid[v]).
// So buggy[v] = hi( key[ lo(key[v]) ] )  — deliberate double indirection.
__global__ void k_buggy() {
    int v = blockIdx.x * blockDim.x + threadIdx.x;
    if (v >= NN) return;
    int p = (int)(g_key[v] & 0xffffffffu);   // oid[v]
    int cid = 0;
    if (p >= 0 && p < NN) cid = (int)(g_key[p] >> 32);
    g_buggy[v] = cid;
}

// ---------------- edge dedup bitmap ----------------
__global__ void k_clearbmp() {
    int c = g_c; if (c > CMAXB) c = CMAXB;
    long long cw = (c + 63) >> 6;
    long long nw = (long long)c * cw;
    if (nw > (long long)BMPW) nw = BMPW;
    long long stride = (long long)gridDim.x * blockDim.x;
    for (long long i = blockIdx.x * (long long)blockDim.x + threadIdx.x; i < nw; i += stride)
        g_bmp[i] = 0ull;
}
__global__ void k_mark(const int* __restrict__ ei) {
    int e = blockIdx.x * blockDim.x + threadIdx.x;
    if (e >= EE) return;
    int s = ei[e], d = ei[EE + e];
    if (s == d) return;
    int a = g_buggy[s], b = g_buggy[d];
    if (a == b) return;
    int c = g_c;
    if (c > CMAXB) return;
    long long cw = (c + 63) >> 6;
    if (a < 0 || a >= c || b < 0 || b >= c) return;
    long long bit = (long long)a * (cw << 6) + b;
    atomicOr(&g_bmp[bit >> 6], 1ull << (bit & 63));
}
__global__ void k_rowcnt() {
    int a = blockIdx.x * blockDim.x + threadIdx.x;
    int c = g_c;
    if (a >= NN) return;
    if (a >= c || c > CMAXB) { g_rowcnt[a] = 0; return; }
    long long cw = (c + 63) >> 6;
    int cnt = 0;
    for (long long w = 0; w < cw; w++) cnt += __popcll(g_bmp[(long long)a * cw + w]);
    g_rowcnt[a] = cnt;
}

// ---------------- scan B ----------------
__global__ void k_scanB1() {
    __shared__ int sh[1024];
    int n = g_c; if (n > NN) n = NN;
    int b = blockIdx.x, tid = threadIdx.x;
    int idx = b * 1024 + tid;
    int v = (idx < n) ? g_rowcnt[idx] : 0;
    sh[tid] = v;
    __syncthreads();
    for (int d = 1; d < 1024; d <<= 1) {
        int t = (tid >= d) ? sh[tid - d] : 0;
        __syncthreads();
        sh[tid] += t;
        __syncthreads();
    }
    if (idx < n) g_rowincl[idx] = sh[tid];
    if (tid == 1023) g_aux[b] = sh[1023];
}
__global__ void k_scanB2() {
    int run = 0;
    for (int b = 0; b < 98; b++) { int t = g_aux[b]; g_aux[b] = run; run += t; }
}
__global__ void k_scanB3() {
    int n = g_c; if (n > NN) n = NN;
    int idx = blockIdx.x * 1024 + threadIdx.x;
    if (idx < n) g_rowincl[idx] += g_aux[idx >> 10];
}
__global__ void k_setE() {
    int c = g_c;
    g_Etot = (c > 0 && c <= NN) ? g_rowincl[c - 1] : 0;
}

// ---------------- x_p = segment_max ----------------
__global__ void k_xclear() {
    long long i = blockIdx.x * (long long)blockDim.x + threadIdx.x;
    if (i < (long long)NN * FD) g_enc[i] = 0u;
}
__global__ void k_xmax(const float* __restrict__ x) {
    long long i = blockIdx.x * (long long)blockDim.x + threadIdx.x;
    if (i >= (long long)NN * FD) return;
    int v = (int)(i / FD), f = (int)(i % FD);
    int cl = g_cluster[v];
    if (cl < 0 || cl >= NN) return;
    unsigned u = __float_as_uint(x[i]);
    u = (u >> 31) ? ~u : (u | 0x80000000u);
    atomicMax(&g_enc[(long long)cl * FD + f], u);
}
__global__ void k_xout(float* __restrict__ out, long long osz) {
    long long i = blockIdx.x * (long long)blockDim.x + threadIdx.x;
    if (i >= (long long)g_c * FD || i >= osz) return;
    unsigned u = g_enc[i];
    unsigned bits = (u & 0x80000000u) ? (u ^ 0x80000000u) : ~u;
    out[i] = __uint_as_float(bits);
}

// ---------------- new_ei emission ----------------
__global__ void k_emit(float* __restrict__ out, long long osz) {
    int a = blockIdx.x * blockDim.x + threadIdx.x;
    int c = g_c;
    if (a >= c || c > CMAXB) return;
    long long cw = (c + 63) >> 6;
    int base = g_rowincl[a] - g_rowcnt[a];
    long long eoff = (long long)FD * c;
    int Et = g_Etot;
    int cnt = 0;
    for (long long w = 0; w < cw; w++) {
        ull u = g_bmp[(long long)a * cw + w];
        while (u) {
            int bpos = __ffsll((long long)u) - 1;
            int b = (int)(w * 64 + bpos);
            long long p0 = eoff + base + cnt;
            long long p1 = eoff + Et + base + cnt;
            if (p0 >= 0 && p0 < osz) out[p0] = (float)a;
            if (p1 >= 0 && p1 < osz) out[p1] = (float)b;
            cnt++;
            u &= (u - 1);
        }
    }
}

// ---------------- pos_p ----------------
__global__ void k_posout(const float* __restrict__ pos, float* __restrict__ out,
                         long long osz) {
    int i = blockIdx.x * blockDim.x + threadIdx.x;
    int c = g_c;
    if (i >= 3 * c) return;
    int j = i / 3, d = i % 3;
    int ctr = g_centers[j];
    if (ctr < 0 || ctr >= NN) return;
    long long off = (long long)FD * c + 2LL * g_Etot + i;
    if (off >= 0 && off < osz)
        out[off] = pos[(long long)ctr * 3 + d];
}

// ---------------- host-side sort driver (launches only) ----------------
static void run_sort() {
    k_sort_local<<<MSEL / 2048, 1024>>>();
    for (int k2 = 4096; k2 <= MSEL; k2 <<= 1) {
        for (int j = k2 >> 1; j >= 2048; j >>= 1)
            k_bitonic<<<MSEL / 256, 256>>>(j, k2);
        k_merge_local<<<MSEL / 2048, 1024>>>(k2);
    }
}

// ---------------- launch ----------------
extern "C" void kernel_launch(void* const* d_in, const int* in_sizes, int n_in,
                              void* d_out, int out_size) {
    const float* x     = (const float*)d_in[0];
    const int*   ei    = (const int*)d_in[1];
    const float* pos   = (const float*)d_in[2];
    const float* wroot = (const float*)d_in[3];
    const float* wrel  = (const float*)d_in[4];
    const float* bb    = (const float*)d_in[5];
    float* out = (float*)d_out;
    long long osz = (long long)out_size;

    k_init<<<(NN + 255) / 256, 256>>>();
    k_dots<<<(NN + 7) / 8, 256>>>(x, pos, wroot, wrel);
    k_edge1<<<(EE + 255) / 256, 256>>>(ei);
    k_minred<<<(NN + 255) / 256, 256>>>();
    k_kcalc<<<1, 1>>>();
    k_key<<<MSEL / 256, 256>>>(bb);
    run_sort();                                   // sel order
    k_scanA1<<<98, 1024>>>();
    k_scanA2<<<1, 1>>>();
    k_scanA3<<<98, 1024>>>();
    k_fillself<<<98, 1024>>>();
    k_adjE<<<(EE + 255) / 256, 256>>>(ei);
    k_peel<<<1, 1024>>>();
    k_key2<<<MSEL / 256, 256>>>();
    run_sort();                                   // concat order (cluster, node)
    k_clearbmp<<<2048, 256>>>();
    k_buggy<<<(NN + 255) / 256, 256>>>();
    k_mark<<<(EE + 255) / 256, 256>>>(ei);
    k_rowcnt<<<(NN + 255) / 256, 256>>>();
    k_scanB1<<<98, 1024>>>();
    k_scanB2<<<1, 1>>>();
    k_scanB3<<<98, 1024>>>();
    k_setE<<<1, 1>>>();
    k_xclear<<<(NN * FD + 255) / 256, 256>>>();
    k_xmax<<<(NN * FD + 255) / 256, 256>>>(x);
    k_xout<<<(NN * FD + 255) / 256, 256>>>(out, osz);
    k_emit<<<(NN + 255) / 256, 256>>>(out, osz);
    k_posout<<<(3 * NN + 255) / 256, 256>>>(pos, out, osz);
}

// round 6
// speedup vs baseline: 1.6060x; 1.4347x over previous
#include <cuda_runtime.h>
#include <math.h>
#include <stdint.h>

typedef unsigned long long ull;

// ---------------- problem constants ----------------
#define NN 100000
#define EE 1600000
#define FD 125
#define PD 3
#define MSEL 131072            // pow2 >= NN
#define NBLK 112               // persistent blocks (<=148 SMs: all wave-1 resident)
#define NT (NBLK*256)          // grid threads = 28672
#define BB 112                 // max speculative batch = NBLK
#define SFC2 4096              // smem frontier capacity per buffer
#define OFC 16384              // global frontier overflow per slot (slots>0)
#define BMPW (1u<<24)          // 2^24 words = 2^30 bits bitmap (c <= 32768)
#define CMAXB 32768
#define QSCALE 17179869184.0   // 2^34 fixed-point scale
#define QINV   (1.0/17179869184.0)

// ---------------- static device scratch ----------------
__device__ double  g_sroot[NN];
__device__ double  g_srel[NN];
__device__ long long g_qrel[NN];
__device__ ull     g_relfix[NN];
__device__ int     g_deg[NN];
__device__ int     g_indptr[NN + 1];
__device__ int     g_fill[NN];
__device__ int     g_adj[NN + EE];
__device__ ull     g_key[MSEL];
__device__ int     g_cluster[NN];
__device__ int     g_centers[NN];
__device__ int     g_buggy[NN];
__device__ int     g_f0[NN];           // slot-0 frontier overflow (never truncates)
__device__ int     g_f1[NN];
__device__ int     g_ofA[BB][OFC];     // per-slot frontier overflow
__device__ int     g_ofB[BB][OFC];
__device__ unsigned g_mark[NN];        // speculative marks: (epoch<<10)|(1023-slot)
__device__ int     g_cand[BB];
__device__ int     g_candpos[BB];
__device__ int     g_conflict[BB];
__device__ int     g_aflag[NT];
__device__ unsigned int g_enc[NN * FD];
__device__ ull     g_bmp[BMPW];        // 128MB
__device__ int     g_rowcnt[NN];
__device__ int     g_rowincl[NN];
__device__ int     g_aux[128];
__device__ int     g_selfcnt;
__device__ int     g_degmin;
__device__ int     g_depth;
__device__ int     g_c;
__device__ int     g_Etot;
// persistent-kernel coordination
__device__ int     g_epoch, g_P, g_C, g_found, g_selDone, g_scanbase, g_batch;
__device__ int     g_barArrive, g_barGen;

// ---------------- init ----------------
__global__ void k_init() {
    int v = blockIdx.x * blockDim.x + threadIdx.x;
    if (v < NN) {
        g_deg[v] = 1;        // appended self-loop
        g_relfix[v] = 0ull;
        g_cluster[v] = -1;
        g_mark[v] = 0u;
    }
    if (v < BB) g_conflict[v] = 0;
    if (v == 0) {
        g_selfcnt = 0; g_degmin = 0x7fffffff;
        g_epoch = 1; g_P = 0; g_C = 0; g_batch = 2;
        g_barArrive = 0; g_barGen = 0;
    }
}

// ---------------- per-node 128-dim dots (fp64, warp per node) ----------------
__global__ void k_dots(const float* __restrict__ x, const float* __restrict__ pos,
                       const float* __restrict__ wroot, const float* __restrict__ wrel) {
    int tid = threadIdx.x;
    int warp = tid >> 5, lane = tid & 31;
    int v = blockIdx.x * 8 + warp;
    if (v >= NN) return;
    double ar = 0.0, rr = 0.0;
    for (int d = lane; d < 128; d += 32) {
        double val = (d < FD) ? (double)x[(size_t)v * FD + d]
                              : (double)pos[(size_t)v * PD + (d - FD)];
        ar += val * (double)wroot[d];
        rr += val * (double)wrel[d];
    }
    for (int o = 16; o > 0; o >>= 1) {
        ar += __shfl_down_sync(0xffffffffu, ar, o);
        rr += __shfl_down_sync(0xffffffffu, rr, o);
    }
    if (lane == 0) {
        g_sroot[v] = ar;
        g_srel[v]  = rr;
        g_qrel[v]  = llrint(rr * QSCALE);
    }
}

// ---------------- edge pass ----------------
__global__ void k_edge1(const int* __restrict__ ei) {
    int e = blockIdx.x * blockDim.x + threadIdx.x;
    if (e >= EE) return;
    int s = ei[e], d = ei[EE + e];
    if (s == d) {
        atomicAdd(&g_selfcnt, 1);
    } else {
        atomicAdd(&g_deg[s], 1);
        atomicAdd(&g_relfix[d], (ull)g_qrel[s]);
    }
}

__global__ void k_minred() {
    int v = blockIdx.x * blockDim.x + threadIdx.x;
    if (v < NN) atomicMin(&g_degmin, g_deg[v]);
}

__global__ void k_kcalc() {
    long long kept = (long long)EE - g_selfcnt;
    double mean = (double)(kept + NN) / (double)NN;
    double b = log(mean - (double)g_degmin);
    double a = log(1.0 / 0.8);
    long long kk = (long long)ceil(a / b);
    int d = (int)kk + 2;
    if (d < 1) d = 1;
    if (d > 16) d = 16;
    g_depth = d;
}

// ---------------- score -> sortable key ----------------
__global__ void k_key(const float* __restrict__ bptr) {
    int i = blockIdx.x * blockDim.x + threadIdx.x;
    if (i >= MSEL) return;
    if (i < NN) {
        double sc = g_sroot[i] + g_srel[i] + (double)(long long)g_relfix[i] * QINV
                  + (double)bptr[0];
        float f = (float)sc;
        unsigned u = __float_as_uint(f);
        u = (u >> 31) ? ~u : (u | 0x80000000u);
        unsigned du = ~u;
        g_key[i] = ((ull)du << 32) | (unsigned)i;
    } else {
        g_key[i] = ~0ull;
    }
}

// ---------------- bitonic sort: global stage + smem-fused stages ----------------
__global__ void k_bitonic(int j, int k2) {
    int i = blockIdx.x * blockDim.x + threadIdx.x;
    int ixj = i ^ j;
    if (ixj > i) {
        ull a = g_key[i], b = g_key[ixj];
        bool up = ((i & k2) == 0);
        if ((a > b) == up) { g_key[i] = b; g_key[ixj] = a; }
    }
}

__global__ void __launch_bounds__(1024) k_sort_local() {
    __shared__ ull sh[2048];
    int base = blockIdx.x * 2048, t = threadIdx.x;
    sh[t] = g_key[base + t];
    sh[t + 1024] = g_key[base + t + 1024];
    __syncthreads();
    for (int k2 = 2; k2 <= 2048; k2 <<= 1) {
        for (int j = k2 >> 1; j > 0; j >>= 1) {
            #pragma unroll
            for (int q = 0; q < 2; q++) {
                int i = t + q * 1024;
                int ixj = i ^ j;
                if (ixj > i) {
                    bool up = (((base + i) & k2) == 0);
                    ull a = sh[i], b = sh[ixj];
                    if ((a > b) == up) { sh[i] = b; sh[ixj] = a; }
                }
            }
            __syncthreads();
        }
    }
    g_key[base + t] = sh[t];
    g_key[base + t + 1024] = sh[t + 1024];
}

__global__ void __launch_bounds__(1024) k_merge_local(int k2) {
    __shared__ ull sh[2048];
    int base = blockIdx.x * 2048, t = threadIdx.x;
    sh[t] = g_key[base + t];
    sh[t + 1024] = g_key[base + t + 1024];
    __syncthreads();
    for (int j = 1024; j > 0; j >>= 1) {
        #pragma unroll
        for (int q = 0; q < 2; q++) {
            int i = t + q * 1024;
            int ixj = i ^ j;
            if (ixj > i) {
                bool up = (((base + i) & k2) == 0);
                ull a = sh[i], b = sh[ixj];
                if ((a > b) == up) { sh[i] = b; sh[ixj] = a; }
            }
        }
        __syncthreads();
    }
    g_key[base + t] = sh[t];
    g_key[base + t + 1024] = sh[t + 1024];
}

// ---------------- scan A: deg -> indptr ----------------
__global__ void k_scanA1() {
    __shared__ int sh[1024];
    int b = blockIdx.x, tid = threadIdx.x;
    int idx = b * 1024 + tid;
    int v = (idx < NN) ? g_deg[idx] : 0;
    sh[tid] = v;
    __syncthreads();
    for (int d = 1; d < 1024; d <<= 1) {
        int t = (tid >= d) ? sh[tid - d] : 0;
        __syncthreads();
        sh[tid] += t;
        __syncthreads();
    }
    if (idx < NN) g_indptr[idx + 1] = sh[tid];
    if (tid == 1023) g_aux[b] = sh[1023];
}
__global__ void k_scanA2() {
    int run = 0;
    for (int b = 0; b < 98; b++) { int t = g_aux[b]; g_aux[b] = run; run += t; }
    g_indptr[0] = 0;
}
__global__ void k_scanA3() {
    int idx = blockIdx.x * 1024 + threadIdx.x;
    if (idx < NN) g_indptr[idx + 1] += g_aux[idx >> 10];
}

__global__ void k_fillself() {
    int v = blockIdx.x * 1024 + threadIdx.x;
    if (v < NN) {
        int p = g_indptr[v];
        g_adj[p] = v;          // self-loop at slot 0
        g_fill[v] = p + 1;
    }
}
__global__ void k_adjE(const int* __restrict__ ei) {
    int e = blockIdx.x * blockDim.x + threadIdx.x;
    if (e >= EE) return;
    int s = ei[e], d = ei[EE + e];
    if (s != d) g_adj[atomicAdd(&g_fill[s], 1)] = d;
}

// ---------------- grid barrier (all NBLK blocks resident) ----------------
__device__ __forceinline__ void gridbar(int* sgen) {
    __syncthreads();
    if (threadIdx.x == 0) {
        int g = *sgen;
        __threadfence();
        if (atomicAdd(&g_barArrive, 1) == NBLK - 1) {
            atomicExch(&g_barArrive, 0);
            __threadfence();
            atomicAdd(&g_barGen, 1);
        } else {
            while (atomicAdd(&g_barGen, 0) < g + 1) { }
        }
        __threadfence();
        *sgen = g + 1;
    }
    __syncthreads();
}

// ------- speculative batched greedy peel (persistent, sequential-equivalent) -------
__global__ void __launch_bounds__(256) k_peel2() {
    __shared__ int sfA[SFC2], sfB[SFC2];
    __shared__ int s_gen, s_next, s_abort, s_fsz, s_commit;
    __shared__ int s_pref[256];
    int tid = threadIdx.x;
    int blk = blockIdx.x;
    if (tid == 0) s_gen = g_barGen;
    __syncthreads();
    int depth = g_depth;

    for (int round = 0; round < NN; round++) {
        // ---- round top: block0 resets selection state ----
        if (blk == 0 && tid == 0) { g_found = 0; g_scanbase = g_P; g_selDone = 0; }
        gridbar(&s_gen);

        // ---- candidate selection: first `batch` alive in sel order ----
        while (true) {
            int scanb = g_scanbase;
            int tg = blk * 256 + tid;
            int pos = scanb + tg;
            int fl = 0;
            if (pos < NN) {
                int s = (int)(g_key[pos] & 0xffffffffu);
                if (g_cluster[s] == -1) fl = 1;
            }
            g_aflag[tg] = fl;
            gridbar(&s_gen);
            if (blk == 0) {
                int found0 = g_found;
                int batch = g_batch;
                int need = batch - found0;
                const int FPT = NT / 256;            // 112 flags per thread
                int base = tid * FPT;
                int cnt = 0;
                for (int k2 = 0; k2 < FPT; k2++) cnt += g_aflag[base + k2];
                s_pref[tid] = cnt;
                __syncthreads();
                for (int d = 1; d < 256; d <<= 1) {
                    int v = (tid >= d) ? s_pref[tid - d] : 0;
                    __syncthreads();
                    s_pref[tid] += v;
                    __syncthreads();
                }
                int excl = s_pref[tid] - cnt;
                int total = s_pref[255];
                int r = excl;
                for (int k2 = 0; k2 < FPT; k2++) {
                    if (g_aflag[base + k2]) {
                        if (r < need) {
                            int p2 = scanb + base + k2;
                            g_cand[found0 + r] = (int)(g_key[p2] & 0xffffffffu);
                            g_candpos[found0 + r] = p2;
                        }
                        r++;
                    }
                }
                __syncthreads();
                if (tid == 0) {
                    int add = total < need ? total : need;
                    int nf = found0 + add;
                    int nsb = scanb + NT;
                    g_found = nf;
                    g_scanbase = nsb;
                    g_selDone = (nf >= batch || nsb >= NN) ? 1 : 0;
                }
            }
            gridbar(&s_gen);
            if (g_selDone) break;
        }

        int found = g_found;
        int epoch = g_epoch;
        if (found == 0) break;                 // all blocks: done

        // ---- speculative BFS: one block per slot ----
        if (blk < found) {
            int slot = blk;
            int center = g_cand[slot];
            unsigned mykey = ((unsigned)epoch << 10) | (unsigned)(1023 - slot);
            if (tid == 0) {
                s_abort = 0; s_fsz = 0;
                unsigned old = atomicMax(&g_mark[center], mykey);
                if ((old >> 10) == (unsigned)epoch) {
                    int os = 1023 - (int)(old & 1023u);
                    if (os < slot)      { g_conflict[slot] = 1; s_abort = 1; }
                    else if (os > slot) { g_conflict[os] = 1; }
                }
                if (!s_abort) { sfA[0] = center; s_fsz = 1; }
            }
            __syncthreads();
            int cur = 0;
            for (int lev = 0; lev < depth; lev++) {
                if (s_abort || s_fsz == 0) break;
                if (tid == 0) s_next = 0;
                __syncthreads();
                int fsz = s_fsz;
                for (int i = tid; i < fsz; i += 256) {
                    int u;
                    if (i < SFC2)       u = cur ? sfB[i] : sfA[i];
                    else if (slot == 0) u = cur ? g_f1[i - SFC2] : g_f0[i - SFC2];
                    else                u = cur ? g_ofB[slot][i - SFC2] : g_ofA[slot][i - SFC2];
                    int e0 = g_indptr[u] + 1, e1 = g_indptr[u + 1];  // skip self slot
                    for (int e = e0; e < e1; e++) {
                        int w = g_adj[e];
                        if (g_cluster[w] != -1) continue;
                        unsigned old = atomicMax(&g_mark[w], mykey);
                        bool own;
                        if ((old >> 10) != (unsigned)epoch) own = true;
                        else {
                            int os = 1023 - (int)(old & 1023u);
                            if (os == slot) continue;
                            if (os < slot) { g_conflict[slot] = 1; s_abort = 1; continue; }
                            g_conflict[os] = 1; own = true;
                        }
                        if (own) {
                            int j = atomicAdd(&s_next, 1);
                            int nc = cur ^ 1;
                            if (j < SFC2) { if (nc) sfB[j] = w; else sfA[j] = w; }
                            else if (slot == 0) { if (nc) g_f1[j - SFC2] = w; else g_f0[j - SFC2] = w; }
                            else if (j < SFC2 + OFC) { if (nc) g_ofB[slot][j - SFC2] = w; else g_ofA[slot][j - SFC2] = w; }
                            else { g_conflict[slot] = 1; s_abort = 1; }
                        }
                    }
                }
                __syncthreads();
                if (tid == 0) s_fsz = s_next;
                cur ^= 1;
                __syncthreads();
            }
        }
        gridbar(&s_gen);

        // ---- commit prefix: first conflicting slot bounds the commit ----
        if (tid == 0) s_commit = found;
        __syncthreads();
        for (int s = tid; s < found; s += 256)
            if (g_conflict[s]) atomicMin(&s_commit, s);
        __syncthreads();
        int committed = s_commit;             // >= 1 always (slot 0 never conflicts)
        int C = g_C;

        for (int v = blk * 256 + tid; v < NN; v += NT) {
            unsigned m = g_mark[v];
            if ((m >> 10) == (unsigned)epoch) {
                int s = 1023 - (int)(m & 1023u);
                if (s < committed) g_cluster[v] = C + s;
            }
        }
        if (blk == 0)
            for (int s = tid; s < committed; s += 256)
                g_centers[C + s] = g_cand[s];
        gridbar(&s_gen);

        // ---- round update ----
        if (blk == 0) {
            for (int s = tid; s < found; s += 256) g_conflict[s] = 0;
            if (tid == 0) {
                g_C = C + committed;
                g_P = g_candpos[committed - 1] + 1;
                g_epoch = epoch + 1;
                int nb = committed * 2;
                if (nb < 2) nb = 2;
                if (nb > BB) nb = BB;
                g_batch = nb;
            }
        }
        gridbar(&s_gen);
    }
    if (blk == 0 && tid == 0) g_c = g_C;
}

// ---------------- concat reconstruction: key = (cluster<<32 | node) ----------------
__global__ void k_key2() {
    int i = blockIdx.x * blockDim.x + threadIdx.x;
    if (i >= MSEL) return;
    if (i < NN) {
        int cl = g_cluster[i];
        unsigned uc = (cl < 0) ? 0x7fffffffu : (unsigned)cl;
        g_key[i] = ((ull)uc << 32) | (unsigned)i;
    } else {
        g_key[i] = ~0ull;
    }
}

// After sort: position p holds key[p] = (cid[p]<<32 | oid[p]).
// Reference: clusters_buggy[v] = cid[ oid[v] ]  (cluster-id AT POSITION oid[v]).
__global__ void k_buggy() {
    int v = blockIdx.x * blockDim.x + threadIdx.x;
    if (v >= NN) return;
    int p = (int)(g_key[v] & 0xffffffffu);   // oid[v]
    int cid = 0;
    if (p >= 0 && p < NN) cid = (int)(g_key[p] >> 32);
    g_buggy[v] = cid;
}

// ---------------- edge dedup bitmap ----------------
__global__ void k_clearbmp() {
    int c = g_c; if (c > CMAXB) c = CMAXB;
    long long cw = (c + 63) >> 6;
    long long nw = (long long)c * cw;
    if (nw > (long long)BMPW) nw = BMPW;
    long long stride = (long long)gridDim.x * blockDim.x;
    for (long long i = blockIdx.x * (long long)blockDim.x + threadIdx.x; i < nw; i += stride)
        g_bmp[i] = 0ull;
}
__global__ void k_mark(const int* __restrict__ ei) {
    int e = blockIdx.x * blockDim.x + threadIdx.x;
    if (e >= EE) return;
    int s = ei[e], d = ei[EE + e];
    if (s == d) return;
    int a = g_buggy[s], b = g_buggy[d];
    if (a == b) return;
    int c = g_c;
    if (c > CMAXB) return;
    long long cw = (c + 63) >> 6;
    if (a < 0 || a >= c || b < 0 || b >= c) return;
    long long bit = (long long)a * (cw << 6) + b;
    atomicOr(&g_bmp[bit >> 6], 1ull << (bit & 63));
}
__global__ void k_rowcnt() {
    int a = blockIdx.x * blockDim.x + threadIdx.x;
    int c = g_c;
    if (a >= NN) return;
    if (a >= c || c > CMAXB) { g_rowcnt[a] = 0; return; }
    long long cw = (c + 63) >> 6;
    int cnt = 0;
    for (long long w = 0; w < cw; w++) cnt += __popcll(g_bmp[(long long)a * cw + w]);
    g_rowcnt[a] = cnt;
}

// ---------------- scan B ----------------
__global__ void k_scanB1() {
    __shared__ int sh[1024];
    int n = g_c; if (n > NN) n = NN;
    int b = blockIdx.x, tid = threadIdx.x;
    int idx = b * 1024 + tid;
    int v = (idx < n) ? g_rowcnt[idx] : 0;
    sh[tid] = v;
    __syncthreads();
    for (int d = 1; d < 1024; d <<= 1) {
        int t = (tid >= d) ? sh[tid - d] : 0;
        __syncthreads();
        sh[tid] += t;
        __syncthreads();
    }
    if (idx < n) g_rowincl[idx] = sh[tid];
    if (tid == 1023) g_aux[b] = sh[1023];
}
__global__ void k_scanB2() {
    int run = 0;
    for (int b = 0; b < 98; b++) { int t = g_aux[b]; g_aux[b] = run; run += t; }
}
__global__ void k_scanB3() {
    int n = g_c; if (n > NN) n = NN;
    int idx = blockIdx.x * 1024 + threadIdx.x;
    if (idx < n) g_rowincl[idx] += g_aux[idx >> 10];
}
__global__ void k_setE() {
    int c = g_c;
    g_Etot = (c > 0 && c <= NN) ? g_rowincl[c - 1] : 0;
}

// ---------------- x_p = segment_max ----------------
__global__ void k_xclear() {
    long long i = blockIdx.x * (long long)blockDim.x + threadIdx.x;
    if (i < (long long)NN * FD) g_enc[i] = 0u;
}
__global__ void k_xmax(const float* __restrict__ x) {
    long long i = blockIdx.x * (long long)blockDim.x + threadIdx.x;
    if (i >= (long long)NN * FD) return;
    int v = (int)(i / FD), f = (int)(i % FD);
    int cl = g_cluster[v];
    if (cl < 0 || cl >= NN) return;
    unsigned u = __float_as_uint(x[i]);
    u = (u >> 31) ? ~u : (u | 0x80000000u);
    atomicMax(&g_enc[(long long)cl * FD + f], u);
}
__global__ void k_xout(float* __restrict__ out, long long osz) {
    long long i = blockIdx.x * (long long)blockDim.x + threadIdx.x;
    if (i >= (long long)g_c * FD || i >= osz) return;
    unsigned u = g_enc[i];
    unsigned bits = (u & 0x80000000u) ? (u ^ 0x80000000u) : ~u;
    out[i] = __uint_as_float(bits);
}

// ---------------- new_ei emission ----------------
__global__ void k_emit(float* __restrict__ out, long long osz) {
    int a = blockIdx.x * blockDim.x + threadIdx.x;
    int c = g_c;
    if (a >= c || c > CMAXB) return;
    long long cw = (c + 63) >> 6;
    int base = g_rowincl[a] - g_rowcnt[a];
    long long eoff = (long long)FD * c;
    int Et = g_Etot;
    int cnt = 0;
    for (long long w = 0; w < cw; w++) {
        ull u = g_bmp[(long long)a * cw + w];
        while (u) {
            int bpos = __ffsll((long long)u) - 1;
            int b = (int)(w * 64 + bpos);
            long long p0 = eoff + base + cnt;
            long long p1 = eoff + Et + base + cnt;
            if (p0 >= 0 && p0 < osz) out[p0] = (float)a;
            if (p1 >= 0 && p1 < osz) out[p1] = (float)b;
            cnt++;
            u &= (u - 1);
        }
    }
}

// ---------------- pos_p ----------------
__global__ void k_posout(const float* __restrict__ pos, float* __restrict__ out,
                         long long osz) {
    int i = blockIdx.x * blockDim.x + threadIdx.x;
    int c = g_c;
    if (i >= 3 * c) return;
    int j = i / 3, d = i % 3;
    int ctr = g_centers[j];
    if (ctr < 0 || ctr >= NN) return;
    long long off = (long long)FD * c + 2LL * g_Etot + i;
    if (off >= 0 && off < osz)
        out[off] = pos[(long long)ctr * 3 + d];
}

// ---------------- host-side sort driver (launches only) ----------------
static void run_sort() {
    k_sort_local<<<MSEL / 2048, 1024>>>();
    for (int k2 = 4096; k2 <= MSEL; k2 <<= 1) {
        for (int j = k2 >> 1; j >= 2048; j >>= 1)
            k_bitonic<<<MSEL / 256, 256>>>(j, k2);
        k_merge_local<<<MSEL / 2048, 1024>>>(k2);
    }
}

// ---------------- launch ----------------
extern "C" void kernel_launch(void* const* d_in, const int* in_sizes, int n_in,
                              void* d_out, int out_size) {
    const float* x     = (const float*)d_in[0];
    const int*   ei    = (const int*)d_in[1];
    const float* pos   = (const float*)d_in[2];
    const float* wroot = (const float*)d_in[3];
    const float* wrel  = (const float*)d_in[4];
    const float* bb    = (const float*)d_in[5];
    float* out = (float*)d_out;
    long long osz = (long long)out_size;

    k_init<<<(NN + 255) / 256, 256>>>();
    k_dots<<<(NN + 7) / 8, 256>>>(x, pos, wroot, wrel);
    k_edge1<<<(EE + 255) / 256, 256>>>(ei);
    k_minred<<<(NN + 255) / 256, 256>>>();
    k_kcalc<<<1, 1>>>();
    k_key<<<MSEL / 256, 256>>>(bb);
    run_sort();                                   // sel order
    k_scanA1<<<98, 1024>>>();
    k_scanA2<<<1, 1>>>();
    k_scanA3<<<98, 1024>>>();
    k_fillself<<<98, 1024>>>();
    k_adjE<<<(EE + 255) / 256, 256>>>(ei);
    k_peel2<<<NBLK, 256>>>();
    k_key2<<<MSEL / 256, 256>>>();
    run_sort();                                   // concat order (cluster, node)
    k_clearbmp<<<2048, 256>>>();
    k_buggy<<<(NN + 255) / 256, 256>>>();
    k_mark<<<(EE + 255) / 256, 256>>>(ei);
    k_rowcnt<<<(NN + 255) / 256, 256>>>();
    k_scanB1<<<98, 1024>>>();
    k_scanB2<<<1, 1>>>();
    k_scanB3<<<98, 1024>>>();
    k_setE<<<1, 1>>>();
    k_xclear<<<(NN * FD + 255) / 256, 256>>>();
    k_xmax<<<(NN * FD + 255) / 256, 256>>>(x);
    k_xout<<<(NN * FD + 255) / 256, 256>>>(out, osz);
    k_emit<<<(NN + 255) / 256, 256>>>(out, osz);
    k_posout<<<(3 * NN + 255) / 256, 256>>>(pos, out, osz);
}

// round 7
// speedup vs baseline: 1.9376x; 1.2065x over previous
#include <cuda_runtime.h>
#include <math.h>
#include <stdint.h>

typedef unsigned long long ull;

// ---------------- problem constants ----------------
#define NN 100000
#define EE 1600000
#define FD 125
#define PD 3
#define MSEL 131072            // pow2 >= NN
#define NBLK 128               // persistent blocks (<=148 SMs: all wave-1 resident)
#define NT (NBLK*256)          // grid threads = 32768
#define BB 128                 // speculative batch = NBLK
#define REGC 16384             // per-slot region capacity (slots > 0)
#define BMPW (1u<<24)          // 2^24 words = 2^30 bits bitmap (c <= 32768)
#define CMAXB 32768
#define QSCALE 17179869184.0   // 2^34 fixed-point scale
#define QINV   (1.0/17179869184.0)

// ---------------- static device scratch ----------------
__device__ double  g_sroot[NN];
__device__ double  g_srel[NN];
__device__ long long g_qrel[NN];
__device__ ull     g_relfix[NN];
__device__ int     g_deg[NN];
__device__ int     g_indptr[NN + 1];
__device__ int     g_fill[NN];
__device__ int     g_adj[NN + EE];
__device__ ull     g_key[MSEL];
__device__ int     g_cluster[NN];
__device__ int     g_centers[NN];
__device__ int     g_buggy[NN];
__device__ int     g_f0[NN];           // slot-0 region list (never truncates)
__device__ int     g_reg[BB][REGC];    // per-slot region lists (slots 1..BB-1)
__device__ int     g_regsz[BB];
__device__ unsigned g_mark[NN];        // speculative marks: (epoch<<10)|(1023-slot)
__device__ int     g_cand[BB];
__device__ int     g_candpos[BB];
__device__ int     g_conf[2][BB];      // conflict flags, double-buffered by round parity
__device__ int     g_aflag[NT];
__device__ unsigned int g_enc[NN * FD];
__device__ ull     g_bmp[BMPW];        // 128MB
__device__ int     g_rowcnt[NN];
__device__ int     g_rowincl[NN];
__device__ int     g_aux[128];
__device__ int     g_selfcnt;
__device__ int     g_degmin;
__device__ int     g_depth;
__device__ int     g_c;
__device__ int     g_Etot;
// persistent-kernel coordination
__device__ int     g_epoch, g_P, g_C, g_found, g_selDone, g_scanbase;
__device__ int     g_barArrive, g_barGen;

// ---------------- init ----------------
__global__ void k_init() {
    int v = blockIdx.x * blockDim.x + threadIdx.x;
    if (v < NN) {
        g_deg[v] = 1;        // appended self-loop
        g_relfix[v] = 0ull;
        g_cluster[v] = -1;
        g_mark[v] = 0u;
    }
    if (v < BB) { g_conf[0][v] = 0; g_conf[1][v] = 0; g_regsz[v] = 0; }
    if (v == 0) {
        g_selfcnt = 0; g_degmin = 0x7fffffff;
        g_epoch = 1; g_P = 0; g_C = 0;
        g_found = 0; g_scanbase = 0; g_selDone = 0;
        g_barArrive = 0; g_barGen = 0;
    }
}

// ---------------- per-node 128-dim dots (fp64, warp per node) ----------------
__global__ void k_dots(const float* __restrict__ x, const float* __restrict__ pos,
                       const float* __restrict__ wroot, const float* __restrict__ wrel) {
    int tid = threadIdx.x;
    int warp = tid >> 5, lane = tid & 31;
    int v = blockIdx.x * 8 + warp;
    if (v >= NN) return;
    double ar = 0.0, rr = 0.0;
    for (int d = lane; d < 128; d += 32) {
        double val = (d < FD) ? (double)x[(size_t)v * FD + d]
                              : (double)pos[(size_t)v * PD + (d - FD)];
        ar += val * (double)wroot[d];
        rr += val * (double)wrel[d];
    }
    for (int o = 16; o > 0; o >>= 1) {
        ar += __shfl_down_sync(0xffffffffu, ar, o);
        rr += __shfl_down_sync(0xffffffffu, rr, o);
    }
    if (lane == 0) {
        g_sroot[v] = ar;
        g_srel[v]  = rr;
        g_qrel[v]  = llrint(rr * QSCALE);
    }
}

// ---------------- edge pass ----------------
__global__ void k_edge1(const int* __restrict__ ei) {
    int e = blockIdx.x * blockDim.x + threadIdx.x;
    if (e >= EE) return;
    int s = ei[e], d = ei[EE + e];
    if (s == d) {
        atomicAdd(&g_selfcnt, 1);
    } else {
        atomicAdd(&g_deg[s], 1);
        atomicAdd(&g_relfix[d], (ull)g_qrel[s]);
    }
}

__global__ void k_minred() {
    int v = blockIdx.x * blockDim.x + threadIdx.x;
    if (v < NN) atomicMin(&g_degmin, g_deg[v]);
}

__global__ void k_kcalc() {
    long long kept = (long long)EE - g_selfcnt;
    double mean = (double)(kept + NN) / (double)NN;
    double b = log(mean - (double)g_degmin);
    double a = log(1.0 / 0.8);
    long long kk = (long long)ceil(a / b);
    int d = (int)kk + 2;
    if (d < 1) d = 1;
    if (d > 16) d = 16;
    g_depth = d;
}

// ---------------- score -> sortable key ----------------
__global__ void k_key(const float* __restrict__ bptr) {
    int i = blockIdx.x * blockDim.x + threadIdx.x;
    if (i >= MSEL) return;
    if (i < NN) {
        double sc = g_sroot[i] + g_srel[i] + (double)(long long)g_relfix[i] * QINV
                  + (double)bptr[0];
        float f = (float)sc;
        unsigned u = __float_as_uint(f);
        u = (u >> 31) ? ~u : (u | 0x80000000u);
        unsigned du = ~u;
        g_key[i] = ((ull)du << 32) | (unsigned)i;
    } else {
        g_key[i] = ~0ull;
    }
}

// ---------------- bitonic sort: global stage + smem-fused stages ----------------
__global__ void k_bitonic(int j, int k2) {
    int i = blockIdx.x * blockDim.x + threadIdx.x;
    int ixj = i ^ j;
    if (ixj > i) {
        ull a = g_key[i], b = g_key[ixj];
        bool up = ((i & k2) == 0);
        if ((a > b) == up) { g_key[i] = b; g_key[ixj] = a; }
    }
}

__global__ void __launch_bounds__(1024) k_sort_local() {
    __shared__ ull sh[2048];
    int base = blockIdx.x * 2048, t = threadIdx.x;
    sh[t] = g_key[base + t];
    sh[t + 1024] = g_key[base + t + 1024];
    __syncthreads();
    for (int k2 = 2; k2 <= 2048; k2 <<= 1) {
        for (int j = k2 >> 1; j > 0; j >>= 1) {
            #pragma unroll
            for (int q = 0; q < 2; q++) {
                int i = t + q * 1024;
                int ixj = i ^ j;
                if (ixj > i) {
                    bool up = (((base + i) & k2) == 0);
                    ull a = sh[i], b = sh[ixj];
                    if ((a > b) == up) { sh[i] = b; sh[ixj] = a; }
                }
            }
            __syncthreads();
        }
    }
    g_key[base + t] = sh[t];
    g_key[base + t + 1024] = sh[t + 1024];
}

__global__ void __launch_bounds__(1024) k_merge_local(int k2) {
    __shared__ ull sh[2048];
    int base = blockIdx.x * 2048, t = threadIdx.x;
    sh[t] = g_key[base + t];
    sh[t + 1024] = g_key[base + t + 1024];
    __syncthreads();
    for (int j = 1024; j > 0; j >>= 1) {
        #pragma unroll
        for (int q = 0; q < 2; q++) {
            int i = t + q * 1024;
            int ixj = i ^ j;
            if (ixj > i) {
                bool up = (((base + i) & k2) == 0);
                ull a = sh[i], b = sh[ixj];
                if ((a > b) == up) { sh[i] = b; sh[ixj] = a; }
            }
        }
        __syncthreads();
    }
    g_key[base + t] = sh[t];
    g_key[base + t + 1024] = sh[t + 1024];
}

// ---------------- scan A: deg -> indptr ----------------
__global__ void k_scanA1() {
    __shared__ int sh[1024];
    int b = blockIdx.x, tid = threadIdx.x;
    int idx = b * 1024 + tid;
    int v = (idx < NN) ? g_deg[idx] : 0;
    sh[tid] = v;
    __syncthreads();
    for (int d = 1; d < 1024; d <<= 1) {
        int t = (tid >= d) ? sh[tid - d] : 0;
        __syncthreads();
        sh[tid] += t;
        __syncthreads();
    }
    if (idx < NN) g_indptr[idx + 1] = sh[tid];
    if (tid == 1023) g_aux[b] = sh[1023];
}
__global__ void k_scanA2() {
    int run = 0;
    for (int b = 0; b < 98; b++) { int t = g_aux[b]; g_aux[b] = run; run += t; }
    g_indptr[0] = 0;
}
__global__ void k_scanA3() {
    int idx = blockIdx.x * 1024 + threadIdx.x;
    if (idx < NN) g_indptr[idx + 1] += g_aux[idx >> 10];
}

__global__ void k_fillself() {
    int v = blockIdx.x * 1024 + threadIdx.x;
    if (v < NN) {
        int p = g_indptr[v];
        g_adj[p] = v;          // self-loop at slot 0
        g_fill[v] = p + 1;
    }
}
__global__ void k_adjE(const int* __restrict__ ei) {
    int e = blockIdx.x * blockDim.x + threadIdx.x;
    if (e >= EE) return;
    int s = ei[e], d = ei[EE + e];
    if (s != d) g_adj[atomicAdd(&g_fill[s], 1)] = d;
}

// ---------------- grid barrier (all NBLK blocks resident) ----------------
__device__ __forceinline__ void gridbar(int* sgen) {
    __syncthreads();
    if (threadIdx.x == 0) {
        int g = *sgen;
        __threadfence();
        if (atomicAdd(&g_barArrive, 1) == NBLK - 1) {
            atomicExch(&g_barArrive, 0);
            __threadfence();
            atomicAdd(&g_barGen, 1);
        } else {
            while (atomicAdd(&g_barGen, 0) < g + 1) { }
        }
        __threadfence();
        *sgen = g + 1;
    }
    __syncthreads();
}

// ------- speculative batched greedy peel v3: region lists, 4 bars/round -------
__global__ void __launch_bounds__(256) k_peel3() {
    __shared__ int s_gen, s_abort, s_hi, s_commit;
    __shared__ int s_pref[256];
    int tid = threadIdx.x;
    int blk = blockIdx.x;
    if (tid == 0) s_gen = g_barGen;
    __syncthreads();
    int depth = g_depth;

    for (int round = 0; round < NN; round++) {
        int par = round & 1;
        // zero own flag in the OTHER parity buffer (used by round+1); safe: last
        // read of that buffer was before the gridbar that ended round-1.
        if (tid == 0) g_conf[par ^ 1][blk] = 0;

        // ---- candidate selection: first BB alive in sel order from g_P ----
        while (true) {
            int scanb = g_scanbase;
            int tg = blk * 256 + tid;
            int pos = scanb + tg;
            int fl = 0;
            if (pos < NN) {
                int s = (int)(g_key[pos] & 0xffffffffu);
                if (g_cluster[s] == -1) fl = 1;
            }
            g_aflag[tg] = fl;
            gridbar(&s_gen);                                   // bar 1
            if (blk == 0) {
                int found0 = g_found;
                int need = BB - found0;
                const int FPT = NT / 256;                      // 128 flags/thread
                int base = tid * FPT;
                int cnt = 0;
                for (int k2 = 0; k2 < FPT; k2++) cnt += g_aflag[base + k2];
                s_pref[tid] = cnt;
                __syncthreads();
                for (int d = 1; d < 256; d <<= 1) {
                    int v = (tid >= d) ? s_pref[tid - d] : 0;
                    __syncthreads();
                    s_pref[tid] += v;
                    __syncthreads();
                }
                int excl = s_pref[tid] - cnt;
                int total = s_pref[255];
                int r = excl;
                for (int k2 = 0; k2 < FPT; k2++) {
                    if (g_aflag[base + k2]) {
                        if (r < need) {
                            int p2 = scanb + base + k2;
                            g_cand[found0 + r] = (int)(g_key[p2] & 0xffffffffu);
                            g_candpos[found0 + r] = p2;
                        }
                        r++;
                    }
                }
                __syncthreads();
                if (tid == 0) {
                    int add = total < need ? total : need;
                    int nf = found0 + add;
                    int nsb = scanb + NT;
                    g_found = nf;
                    g_scanbase = nsb;
                    g_selDone = (nf >= BB || nsb >= NN) ? 1 : 0;
                }
            }
            gridbar(&s_gen);                                   // bar 2
            if (g_selDone) break;
        }

        int found = g_found;
        int epoch = g_epoch;
        if (found == 0) break;

        // ---- speculative BFS: one block per slot, region list w/ level segments ----
        if (blk < found) {
            int slot = blk;
            int* reg = (slot == 0) ? g_f0 : g_reg[slot];
            int cap  = (slot == 0) ? NN : REGC;
            int center = g_cand[slot];
            unsigned mykey = ((unsigned)epoch << 10) | (unsigned)(1023 - slot);
            if (tid == 0) {
                s_abort = 0; s_hi = 0;
                unsigned old = atomicMax(&g_mark[center], mykey);
                if ((old >> 10) == (unsigned)epoch) {
                    int os = 1023 - (int)(old & 1023u);
                    if (os < slot)      { atomicExch(&g_conf[par][slot], 1); s_abort = 1; }
                    else if (os > slot) { atomicExch(&g_conf[par][os], 1); }
                }
                if (!s_abort) { reg[0] = center; s_hi = 1; }
            }
            __syncthreads();
            int lo = 0;
            for (int lev = 0; lev < depth; lev++) {
                if (s_abort) break;
                int hi = s_hi;
                if (hi == lo) break;
                // abort-on-flag: a smaller slot stole from us -> can't commit
                if (tid == 0 && atomicAdd(&g_conf[par][slot], 0)) s_abort = 1;
                __syncthreads();
                if (s_abort) break;
                for (int i = lo + tid; i < hi; i += 256) {
                    int u = reg[i];
                    int e0 = g_indptr[u] + 1, e1 = g_indptr[u + 1];  // skip self slot
                    for (int e = e0; e < e1; e++) {
                        int w = g_adj[e];
                        if (g_cluster[w] != -1) continue;
                        unsigned old = atomicMax(&g_mark[w], mykey);
                        bool own;
                        if ((old >> 10) != (unsigned)epoch) own = true;
                        else {
                            int os = 1023 - (int)(old & 1023u);
                            if (os == slot) continue;
                            if (os < slot) { atomicExch(&g_conf[par][slot], 1); s_abort = 1; continue; }
                            atomicExch(&g_conf[par][os], 1); own = true;
                        }
                        if (own) {
                            int j = atomicAdd(&s_hi, 1);
                            if (j < cap) reg[j] = w;
                            else { atomicExch(&g_conf[par][slot], 1); s_abort = 1; }
                        }
                    }
                }
                __syncthreads();
                lo = hi;
            }
            if (tid == 0) g_regsz[slot] = s_hi < cap ? s_hi : cap;
        }
        gridbar(&s_gen);                                       // bar 3

        // ---- commit boundary: every block computes it from conflict flags ----
        if (tid == 0) s_commit = found;
        __syncthreads();
        for (int s = tid; s < found; s += 256)
            if (atomicAdd(&g_conf[par][s], 0)) atomicMin(&s_commit, s);
        __syncthreads();
        int committed = s_commit;              // >= 1 (slot 0 never flagged)
        int C = g_C;

        // committed slots write their regions
        if (blk < committed) {
            int* reg = (blk == 0) ? g_f0 : g_reg[blk];
            int sz = g_regsz[blk];
            int cid = C + blk;
            for (int i = tid; i < sz; i += 256) g_cluster[reg[i]] = cid;
        }
        if (blk == 0) {
            for (int s = tid; s < committed; s += 256) g_centers[C + s] = g_cand[s];
            if (tid == 0) {
                g_C = C + committed;
                int np = g_candpos[committed - 1] + 1;
                g_P = np;
                g_epoch = epoch + 1;
                g_found = 0; g_scanbase = np; g_selDone = 0;   // next round's state
            }
        }
        gridbar(&s_gen);                                       // bar 4
    }
    if (blk == 0 && tid == 0) g_c = g_C;
}

// ---------------- concat reconstruction: key = (cluster<<32 | node) ----------------
__global__ void k_key2() {
    int i = blockIdx.x * blockDim.x + threadIdx.x;
    if (i >= MSEL) return;
    if (i < NN) {
        int cl = g_cluster[i];
        unsigned uc = (cl < 0) ? 0x7fffffffu : (unsigned)cl;
        g_key[i] = ((ull)uc << 32) | (unsigned)i;
    } else {
        g_key[i] = ~0ull;
    }
}

// After sort: position p holds key[p] = (cid[p]<<32 | oid[p]).
// Reference: clusters_buggy[v] = cid[ oid[v] ]  (cluster-id AT POSITION oid[v]).
__global__ void k_buggy() {
    int v = blockIdx.x * blockDim.x + threadIdx.x;
    if (v >= NN) return;
    int p = (int)(g_key[v] & 0xffffffffu);   // oid[v]
    int cid = 0;
    if (p >= 0 && p < NN) cid = (int)(g_key[p] >> 32);
    g_buggy[v] = cid;
}

// ---------------- edge dedup bitmap ----------------
__global__ void k_clearbmp() {
    int c = g_c; if (c > CMAXB) c = CMAXB;
    long long cw = (c + 63) >> 6;
    long long nw = (long long)c * cw;
    if (nw > (long long)BMPW) nw = BMPW;
    long long stride = (long long)gridDim.x * blockDim.x;
    for (long long i = blockIdx.x * (long long)blockDim.x + threadIdx.x; i < nw; i += stride)
        g_bmp[i] = 0ull;
}
__global__ void k_mark(const int* __restrict__ ei) {
    int e = blockIdx.x * blockDim.x + threadIdx.x;
    if (e >= EE) return;
    int s = ei[e], d = ei[EE + e];
    if (s == d) return;
    int a = g_buggy[s], b = g_buggy[d];
    if (a == b) return;
    int c = g_c;
    if (c > CMAXB) return;
    long long cw = (c + 63) >> 6;
    if (a < 0 || a >= c || b < 0 || b >= c) return;
    long long bit = (long long)a * (cw << 6) + b;
    atomicOr(&g_bmp[bit >> 6], 1ull << (bit & 63));
}
__global__ void k_rowcnt() {
    int a = blockIdx.x * blockDim.x + threadIdx.x;
    int c = g_c;
    if (a >= NN) return;
    if (a >= c || c > CMAXB) { g_rowcnt[a] = 0; return; }
    long long cw = (c + 63) >> 6;
    int cnt = 0;
    for (long long w = 0; w < cw; w++) cnt += __popcll(g_bmp[(long long)a * cw + w]);
    g_rowcnt[a] = cnt;
}

// ---------------- scan B ----------------
__global__ void k_scanB1() {
    __shared__ int sh[1024];
    int n = g_c; if (n > NN) n = NN;
    int b = blockIdx.x, tid = threadIdx.x;
    int idx = b * 1024 + tid;
    int v = (idx < n) ? g_rowcnt[idx] : 0;
    sh[tid] = v;
    __syncthreads();
    for (int d = 1; d < 1024; d <<= 1) {
        int t = (tid >= d) ? sh[tid - d] : 0;
        __syncthreads();
        sh[tid] += t;
        __syncthreads();
    }
    if (idx < n) g_rowincl[idx] = sh[tid];
    if (tid == 1023) g_aux[b] = sh[1023];
}
__global__ void k_scanB2() {
    int run = 0;
    for (int b = 0; b < 98; b++) { int t = g_aux[b]; g_aux[b] = run; run += t; }
}
__global__ void k_scanB3() {
    int n = g_c; if (n > NN) n = NN;
    int idx = blockIdx.x * 1024 + threadIdx.x;
    if (idx < n) g_rowincl[idx] += g_aux[idx >> 10];
}
__global__ void k_setE() {
    int c = g_c;
    g_Etot = (c > 0 && c <= NN) ? g_rowincl[c - 1] : 0;
}

// ---------------- x_p = segment_max ----------------
__global__ void k_xclear() {
    long long i = blockIdx.x * (long long)blockDim.x + threadIdx.x;
    if (i < (long long)NN * FD) g_enc[i] = 0u;
}
__global__ void k_xmax(const float* __restrict__ x) {
    long long i = blockIdx.x * (long long)blockDim.x + threadIdx.x;
    if (i >= (long long)NN * FD) return;
    int v = (int)(i / FD), f = (int)(i % FD);
    int cl = g_cluster[v];
    if (cl < 0 || cl >= NN) return;
    unsigned u = __float_as_uint(x[i]);
    u = (u >> 31) ? ~u : (u | 0x80000000u);
    atomicMax(&g_enc[(long long)cl * FD + f], u);
}
__global__ void k_xout(float* __restrict__ out, long long osz) {
    long long i = blockIdx.x * (long long)blockDim.x + threadIdx.x;
    if (i >= (long long)g_c * FD || i >= osz) return;
    unsigned u = g_enc[i];
    unsigned bits = (u & 0x80000000u) ? (u ^ 0x80000000u) : ~u;
    out[i] = __uint_as_float(bits);
}

// ---------------- new_ei emission ----------------
__global__ void k_emit(float* __restrict__ out, long long osz) {
    int a = blockIdx.x * blockDim.x + threadIdx.x;
    int c = g_c;
    if (a >= c || c > CMAXB) return;
    long long cw = (c + 63) >> 6;
    int base = g_rowincl[a] - g_rowcnt[a];
    long long eoff = (long long)FD * c;
    int Et = g_Etot;
    int cnt = 0;
    for (long long w = 0; w < cw; w++) {
        ull u = g_bmp[(long long)a * cw + w];
        while (u) {
            int bpos = __ffsll((long long)u) - 1;
            int b = (int)(w * 64 + bpos);
            long long p0 = eoff + base + cnt;
            long long p1 = eoff + Et + base + cnt;
            if (p0 >= 0 && p0 < osz) out[p0] = (float)a;
            if (p1 >= 0 && p1 < osz) out[p1] = (float)b;
            cnt++;
            u &= (u - 1);
        }
    }
}

// ---------------- pos_p ----------------
__global__ void k_posout(const float* __restrict__ pos, float* __restrict__ out,
                         long long osz) {
    int i = blockIdx.x * blockDim.x + threadIdx.x;
    int c = g_c;
    if (i >= 3 * c) return;
    int j = i / 3, d = i % 3;
    int ctr = g_centers[j];
    if (ctr < 0 || ctr >= NN) return;
    long long off = (long long)FD * c + 2LL * g_Etot + i;
    if (off >= 0 && off < osz)
        out[off] = pos[(long long)ctr * 3 + d];
}

// ---------------- host-side sort driver (launches only) ----------------
static void run_sort() {
    k_sort_local<<<MSEL / 2048, 1024>>>();
    for (int k2 = 4096; k2 <= MSEL; k2 <<= 1) {
        for (int j = k2 >> 1; j >= 2048; j >>= 1)
            k_bitonic<<<MSEL / 256, 256>>>(j, k2);
        k_merge_local<<<MSEL / 2048, 1024>>>(k2);
    }
}

// ---------------- launch ----------------
extern "C" void kernel_launch(void* const* d_in, const int* in_sizes, int n_in,
                              void* d_out, int out_size) {
    const float* x     = (const float*)d_in[0];
    const int*   ei    = (const int*)d_in[1];
    const float* pos   = (const float*)d_in[2];
    const float* wroot = (const float*)d_in[3];
    const float* wrel  = (const float*)d_in[4];
    const float* bb    = (const float*)d_in[5];
    float* out = (float*)d_out;
    long long osz = (long long)out_size;

    k_init<<<(NN + 255) / 256, 256>>>();
    k_dots<<<(NN + 7) / 8, 256>>>(x, pos, wroot, wrel);
    k_edge1<<<(EE + 255) / 256, 256>>>(ei);
    k_minred<<<(NN + 255) / 256, 256>>>();
    k_kcalc<<<1, 1>>>();
    k_key<<<MSEL / 256, 256>>>(bb);
    run_sort();                                   // sel order
    k_scanA1<<<98, 1024>>>();
    k_scanA2<<<1, 1>>>();
    k_scanA3<<<98, 1024>>>();
    k_fillself<<<98, 1024>>>();
    k_adjE<<<(EE + 255) / 256, 256>>>(ei);
    k_peel3<<<NBLK, 256>>>();
    k_key2<<<MSEL / 256, 256>>>();
    run_sort();                                   // concat order (cluster, node)
    k_clearbmp<<<2048, 256>>>();
    k_buggy<<<(NN + 255) / 256, 256>>>();
    k_mark<<<(EE + 255) / 256, 256>>>(ei);
    k_rowcnt<<<(NN + 255) / 256, 256>>>();
    k_scanB1<<<98, 1024>>>();
    k_scanB2<<<1, 1>>>();
    k_scanB3<<<98, 1024>>>();
    k_setE<<<1, 1>>>();
    k_xclear<<<(NN * FD + 255) / 256, 256>>>();
    k_xmax<<<(NN * FD + 255) / 256, 256>>>(x);
    k_xout<<<(NN * FD + 255) / 256, 256>>>(out, osz);
    k_emit<<<(NN + 255) / 256, 256>>>(out, osz);
    k_posout<<<(3 * NN + 255) / 256, 256>>>(pos, out, osz);
}

// round 9
// speedup vs baseline: 1.9448x; 1.0037x over previous
#include <cuda_runtime.h>
#include <math.h>
#include <stdint.h>

typedef unsigned long long ull;

// ---------------- problem constants ----------------
#define NN 100000
#define EE 1600000
#define FD 125
#define PD 3
#define MSEL 131072            // pow2 >= NN
#define NBLK 128               // persistent blocks (<=148 SMs: all wave-1 resident)
#define NT (NBLK*256)          // grid threads = 32768
#define BB 128                 // speculative batch = NBLK
#define REGC 16384             // per-slot region capacity (slots > 0)
#define BMPW (1u<<24)          // 2^24 words = 2^30 bits bitmap (c <= 32768)
#define CMAXB 32768
#define QSCALE 17179869184.0   // 2^34 fixed-point scale
#define QINV   (1.0/17179869184.0)

// ---------------- static device scratch ----------------
__device__ double  g_sroot[NN];
__device__ double  g_srel[NN];
__device__ long long g_qrel[NN];
__device__ ull     g_relfix[NN];
__device__ int     g_deg[NN];
__device__ int     g_indptr[NN + 1];
__device__ int     g_fill[NN];
__device__ int     g_adj[NN + EE];
__device__ ull     g_key[MSEL];
__device__ int     g_cluster[NN];
__device__ int     g_centers[NN];
__device__ int     g_buggy[NN];
__device__ int     g_f0[NN];           // slot-0 region list (never truncates)
__device__ int     g_reg[BB][REGC];    // per-slot region lists (slots 1..BB-1)
__device__ int     g_regsz[BB];
__device__ unsigned g_mark[NN];        // speculative marks: (epoch<<10)|(1023-slot)
__device__ int     g_cand[BB];
__device__ int     g_candpos[BB];
__device__ int     g_conf[2][BB];      // conflict flags, double-buffered by round parity
__device__ int     g_aflag[NT];
__device__ unsigned int g_enc[NN * FD];
__device__ ull     g_bmp[BMPW];        // 128MB
__device__ int     g_rowcnt[NN];
__device__ int     g_rowincl[NN];
__device__ int     g_aux[128];
__device__ int     g_selfcnt;
__device__ int     g_degmin;
__device__ int     g_depth;
__device__ int     g_c;
__device__ int     g_Etot;
// persistent-kernel coordination
__device__ int     g_epoch, g_P, g_C, g_found, g_selDone, g_scanbase;
__device__ int     g_barArrive, g_barGen;

// ---------------- init ----------------
__global__ void k_init() {
    int v = blockIdx.x * blockDim.x + threadIdx.x;
    if (v < NN) {
        g_deg[v] = 1;        // appended self-loop
        g_relfix[v] = 0ull;
        g_cluster[v] = -1;
        g_mark[v] = 0u;
    }
    if (v < BB) { g_conf[0][v] = 0; g_conf[1][v] = 0; g_regsz[v] = 0; }
    if (v == 0) {
        g_selfcnt = 0; g_degmin = 0x7fffffff;
        g_epoch = 1; g_P = 0; g_C = 0;
        g_found = 0; g_scanbase = 0; g_selDone = 0;
        g_barArrive = 0; g_barGen = 0;
    }
}

// ---------------- per-node 128-dim dots (fp64, warp per node) ----------------
__global__ void k_dots(const float* __restrict__ x, const float* __restrict__ pos,
                       const float* __restrict__ wroot, const float* __restrict__ wrel) {
    int tid = threadIdx.x;
    int warp = tid >> 5, lane = tid & 31;
    int v = blockIdx.x * 8 + warp;
    if (v >= NN) return;
    double ar = 0.0, rr = 0.0;
    for (int d = lane; d < 128; d += 32) {
        double val = (d < FD) ? (double)x[(size_t)v * FD + d]
                              : (double)pos[(size_t)v * PD + (d - FD)];
        ar += val * (double)wroot[d];
        rr += val * (double)wrel[d];
    }
    for (int o = 16; o > 0; o >>= 1) {
        ar += __shfl_down_sync(0xffffffffu, ar, o);
        rr += __shfl_down_sync(0xffffffffu, rr, o);
    }
    if (lane == 0) {
        g_sroot[v] = ar;
        g_srel[v]  = rr;
        g_qrel[v]  = llrint(rr * QSCALE);
    }
}

// ---------------- edge pass ----------------
__global__ void k_edge1(const int* __restrict__ ei) {
    int e = blockIdx.x * blockDim.x + threadIdx.x;
    if (e >= EE) return;
    int s = ei[e], d = ei[EE + e];
    if (s == d) {
        atomicAdd(&g_selfcnt, 1);
    } else {
        atomicAdd(&g_deg[s], 1);
        atomicAdd(&g_relfix[d], (ull)g_qrel[s]);
    }
}

__global__ void k_minred() {
    int v = blockIdx.x * blockDim.x + threadIdx.x;
    if (v < NN) atomicMin(&g_degmin, g_deg[v]);
}

__global__ void k_kcalc() {
    long long kept = (long long)EE - g_selfcnt;
    double mean = (double)(kept + NN) / (double)NN;
    double b = log(mean - (double)g_degmin);
    double a = log(1.0 / 0.8);
    long long kk = (long long)ceil(a / b);
    int d = (int)kk + 2;
    if (d < 1) d = 1;
    if (d > 16) d = 16;
    g_depth = d;
}

// ---------------- score -> sortable key ----------------
__global__ void k_key(const float* __restrict__ bptr) {
    int i = blockIdx.x * blockDim.x + threadIdx.x;
    if (i >= MSEL) return;
    if (i < NN) {
        double sc = g_sroot[i] + g_srel[i] + (double)(long long)g_relfix[i] * QINV
                  + (double)bptr[0];
        float f = (float)sc;
        unsigned u = __float_as_uint(f);
        u = (u >> 31) ? ~u : (u | 0x80000000u);
        unsigned du = ~u;
        g_key[i] = ((ull)du << 32) | (unsigned)i;
    } else {
        g_key[i] = ~0ull;
    }
}

// ---------------- bitonic sort: global stage + smem-fused stages ----------------
__global__ void k_bitonic(int j, int k2) {
    int i = blockIdx.x * blockDim.x + threadIdx.x;
    int ixj = i ^ j;
    if (ixj > i) {
        ull a = g_key[i], b = g_key[ixj];
        bool up = ((i & k2) == 0);
        if ((a > b) == up) { g_key[i] = b; g_key[ixj] = a; }
    }
}

__global__ void __launch_bounds__(1024) k_sort_local() {
    __shared__ ull sh[2048];
    int base = blockIdx.x * 2048, t = threadIdx.x;
    sh[t] = g_key[base + t];
    sh[t + 1024] = g_key[base + t + 1024];
    __syncthreads();
    for (int k2 = 2; k2 <= 2048; k2 <<= 1) {
        for (int j = k2 >> 1; j > 0; j >>= 1) {
            #pragma unroll
            for (int q = 0; q < 2; q++) {
                int i = t + q * 1024;
                int ixj = i ^ j;
                if (ixj > i) {
                    bool up = (((base + i) & k2) == 0);
                    ull a = sh[i], b = sh[ixj];
                    if ((a > b) == up) { sh[i] = b; sh[ixj] = a; }
                }
            }
            __syncthreads();
        }
    }
    g_key[base + t] = sh[t];
    g_key[base + t + 1024] = sh[t + 1024];
}

__global__ void __launch_bounds__(1024) k_merge_local(int k2) {
    __shared__ ull sh[2048];
    int base = blockIdx.x * 2048, t = threadIdx.x;
    sh[t] = g_key[base + t];
    sh[t + 1024] = g_key[base + t + 1024];
    __syncthreads();
    for (int j = 1024; j > 0; j >>= 1) {
        #pragma unroll
        for (int q = 0; q < 2; q++) {
            int i = t + q * 1024;
            int ixj = i ^ j;
            if (ixj > i) {
                bool up = (((base + i) & k2) == 0);
                ull a = sh[i], b = sh[ixj];
                if ((a > b) == up) { sh[i] = b; sh[ixj] = a; }
            }
        }
        __syncthreads();
    }
    g_key[base + t] = sh[t];
    g_key[base + t + 1024] = sh[t + 1024];
}

// ---------------- scan A: deg -> indptr ----------------
__global__ void k_scanA1() {
    __shared__ int sh[1024];
    int b = blockIdx.x, tid = threadIdx.x;
    int idx = b * 1024 + tid;
    int v = (idx < NN) ? g_deg[idx] : 0;
    sh[tid] = v;
    __syncthreads();
    for (int d = 1; d < 1024; d <<= 1) {
        int t = (tid >= d) ? sh[tid - d] : 0;
        __syncthreads();
        sh[tid] += t;
        __syncthreads();
    }
    if (idx < NN) g_indptr[idx + 1] = sh[tid];
    if (tid == 1023) g_aux[b] = sh[1023];
}
__global__ void k_scanA2() {
    int run = 0;
    for (int b = 0; b < 98; b++) { int t = g_aux[b]; g_aux[b] = run; run += t; }
    g_indptr[0] = 0;
}
__global__ void k_scanA3() {
    int idx = blockIdx.x * 1024 + threadIdx.x;
    if (idx < NN) g_indptr[idx + 1] += g_aux[idx >> 10];
}

__global__ void k_fillself() {
    int v = blockIdx.x * 1024 + threadIdx.x;
    if (v < NN) {
        int p = g_indptr[v];
        g_adj[p] = v;          // self-loop at slot 0
        g_fill[v] = p + 1;
    }
}
__global__ void k_adjE(const int* __restrict__ ei) {
    int e = blockIdx.x * blockDim.x + threadIdx.x;
    if (e >= EE) return;
    int s = ei[e], d = ei[EE + e];
    if (s != d) g_adj[atomicAdd(&g_fill[s], 1)] = d;
}

// ---------------- grid barrier (all NBLK blocks resident) ----------------
__device__ __forceinline__ void gridbar(int* sgen) {
    __syncthreads();
    if (threadIdx.x == 0) {
        int g = *sgen;
        __threadfence();
        if (atomicAdd(&g_barArrive, 1) == NBLK - 1) {
            atomicExch(&g_barArrive, 0);
            __threadfence();
            atomicAdd(&g_barGen, 1);
        } else {
            while (atomicAdd(&g_barGen, 0) < g + 1) { }
        }
        __threadfence();
        *sgen = g + 1;
    }
    __syncthreads();
}

// ------- speculative peel v4: commit ALL provably-sequential slots -------
__global__ void __launch_bounds__(256) k_peel4() {
    __shared__ int s_gen, s_abort, s_hi, s_stop;
    __shared__ int s_pref[256];
    __shared__ int s_flag[BB];
    __shared__ int s_rank[BB + 1];   // exclusive rank of unflagged among < s
    int tid = threadIdx.x;
    int blk = blockIdx.x;
    if (tid == 0) s_gen = g_barGen;
    __syncthreads();
    int depth = g_depth;

    for (int round = 0; round < NN; round++) {
        int par = round & 1;
        // zero own flag in the OTHER parity buffer (used by round+1)
        if (tid == 0) g_conf[par ^ 1][blk] = 0;

        // ---- candidate selection: first BB alive in sel order from g_P ----
        while (true) {
            int scanb = g_scanbase;
            int tg = blk * 256 + tid;
            int pos = scanb + tg;
            int fl = 0;
            if (pos < NN) {
                int s = (int)(g_key[pos] & 0xffffffffu);
                if (g_cluster[s] == -1) fl = 1;
            }
            g_aflag[tg] = fl;
            gridbar(&s_gen);                                   // bar 1
            if (blk == 0) {
                int found0 = g_found;
                int need = BB - found0;
                const int FPT = NT / 256;                      // 128 flags/thread
                int base = tid * FPT;
                int cnt = 0;
                for (int k2 = 0; k2 < FPT; k2++) cnt += g_aflag[base + k2];
                s_pref[tid] = cnt;
                __syncthreads();
                for (int d = 1; d < 256; d <<= 1) {
                    int v = (tid >= d) ? s_pref[tid - d] : 0;
                    __syncthreads();
                    s_pref[tid] += v;
                    __syncthreads();
                }
                int excl = s_pref[tid] - cnt;
                int total = s_pref[255];
                int r = excl;
                for (int k2 = 0; k2 < FPT; k2++) {
                    if (g_aflag[base + k2]) {
                        if (r < need) {
                            int p2 = scanb + base + k2;
                            g_cand[found0 + r] = (int)(g_key[p2] & 0xffffffffu);
                            g_candpos[found0 + r] = p2;
                        }
                        r++;
                    }
                }
                __syncthreads();
                if (tid == 0) {
                    int add = total < need ? total : need;
                    int nf = found0 + add;
                    int nsb = scanb + NT;
                    g_found = nf;
                    g_scanbase = nsb;
                    g_selDone = (nf >= BB || nsb >= NN) ? 1 : 0;
                }
            }
            gridbar(&s_gen);                                   // bar 2
            if (g_selDone) break;
        }

        int found = g_found;
        int epoch = g_epoch;
        if (found == 0) break;

        // ---- speculative BFS: one block per slot ----
        if (blk < found) {
            int slot = blk;
            int* reg = (slot == 0) ? g_f0 : g_reg[slot];
            int cap  = (slot == 0) ? NN : REGC;
            int center = g_cand[slot];
            unsigned mykey = ((unsigned)epoch << 10) | (unsigned)(1023 - slot);
            if (tid == 0) {
                s_abort = 0; s_hi = 0;
                unsigned old = atomicMax(&g_mark[center], mykey);
                if ((old >> 10) == (unsigned)epoch) {
                    int os = 1023 - (int)(old & 1023u);
                    if (os < slot)      { atomicExch(&g_conf[par][slot], 1); s_abort = 1; }
                    else if (os > slot) { atomicExch(&g_conf[par][os], 1); }
                }
                if (!s_abort) { reg[0] = center; s_hi = 1; }
            }
            __syncthreads();
            int lo = 0;
            for (int lev = 0; lev < depth; lev++) {
                if (s_abort) break;
                int hi = s_hi;
                if (hi == lo) break;
                if (tid == 0 && atomicAdd(&g_conf[par][slot], 0)) s_abort = 1;
                __syncthreads();
                if (s_abort) break;
                for (int i = lo + tid; i < hi; i += 256) {
                    int u = reg[i];
                    int e0 = g_indptr[u] + 1, e1 = g_indptr[u + 1];  // skip self slot
                    for (int e = e0; e < e1; e++) {
                        int w = g_adj[e];
                        if (g_cluster[w] != -1) continue;
                        unsigned old = atomicMax(&g_mark[w], mykey);
                        bool own;
                        if ((old >> 10) != (unsigned)epoch) own = true;
                        else {
                            int os = 1023 - (int)(old & 1023u);
                            if (os == slot) continue;
                            if (os < slot) { atomicExch(&g_conf[par][slot], 1); s_abort = 1; continue; }
                            atomicExch(&g_conf[par][os], 1); own = true;
                        }
                        if (own) {
                            int j = atomicAdd(&s_hi, 1);
                            if (j < cap) reg[j] = w;
                            else { atomicExch(&g_conf[par][slot], 1); s_abort = 1; }
                        }
                    }
                }
                __syncthreads();
                lo = hi;
            }
            if (tid == 0) g_regsz[slot] = s_hi < cap ? s_hi : cap;
        }
        gridbar(&s_gen);                                       // bar 3

        // ---- commit analysis (redundant in every block, no extra bar) ----
        // flagged slot is DEAD (skippable) iff its center's mark is held by a
        // smaller UNFLAGGED slot (that slot commits and kills the center).
        // stop = first flagged slot that is not dead. Commit all unflagged < stop.
        for (int s = tid; s < found; s += 256) s_flag[s] = g_conf[par][s];
        if (tid == 0) s_stop = found;
        __syncthreads();
        for (int s = tid; s < found; s += 256) {
            if (s_flag[s]) {
                int dead = 0;
                unsigned m = g_mark[g_cand[s]];
                if ((m >> 10) == (unsigned)epoch) {
                    int os = 1023 - (int)(m & 1023u);
                    if (os < s && os < found && !s_flag[os]) dead = 1;
                }
                if (!dead) atomicMin(&s_stop, s);
            }
        }
        __syncthreads();
        int stop = s_stop;                       // >= 1 (slot 0 never flagged)
        // exclusive rank of unflagged among slots < stop (serial scan over <=128 by t0)
        if (tid == 0) {
            int r = 0;
            for (int s = 0; s < stop; s++) { s_rank[s] = r; if (!s_flag[s]) r++; }
            s_rank[stop] = r;                    // total committed
        }
        __syncthreads();
        int C = g_C;
        int ncommit = s_rank[stop];

        // committed slots write their regions with re-ranked ids
        if (blk < stop && !s_flag[blk]) {
            int* reg = (blk == 0) ? g_f0 : g_reg[blk];
            int sz = g_regsz[blk];
            int cid = C + s_rank[blk];
            for (int i = tid; i < sz; i += 256) g_cluster[reg[i]] = cid;
        }
        if (blk == 0) {
            for (int s = tid; s < stop; s += 256)
                if (!s_flag[s]) g_centers[C + s_rank[s]] = g_cand[s];
            if (tid == 0) {
                g_C = C + ncommit;
                int np = g_candpos[stop - 1] + 1;
                g_P = np;
                g_epoch = epoch + 1;
                g_found = 0; g_scanbase = np; g_selDone = 0;
            }
        }
        gridbar(&s_gen);                                       // bar 4
    }
    if (blk == 0 && tid == 0) g_c = g_C;
}

// ---------------- concat reconstruction: key = (cluster<<32 | node) ----------------
__global__ void k_key2() {
    int i = blockIdx.x * blockDim.x + threadIdx.x;
    if (i >= MSEL) return;
    if (i < NN) {
        int cl = g_cluster[i];
        unsigned uc = (cl < 0) ? 0x7fffffffu : (unsigned)cl;
        g_key[i] = ((ull)uc << 32) | (unsigned)i;
    } else {
        g_key[i] = ~0ull;
    }
}

// After sort: position p holds key[p] = (cid[p]<<32 | oid[p]).
// Reference: clusters_buggy[v] = cid[ oid[v] ]  (cluster-id AT POSITION oid[v]).
__global__ void k_buggy() {
    int v = blockIdx.x * blockDim.x + threadIdx.x;
    if (v >= NN) return;
    int p = (int)(g_key[v] & 0xffffffffu);   // oid[v]
    int cid = 0;
    if (p >= 0 && p < NN) cid = (int)(g_key[p] >> 32);
    g_buggy[v] = cid;
}

// ---------------- edge dedup bitmap ----------------
__global__ void k_clearbmp() {
    int c = g_c; if (c > CMAXB) c = CMAXB;
    long long cw = (c + 63) >> 6;
    long long nw = (long long)c * cw;
    if (nw > (long long)BMPW) nw = BMPW;
    long long stride = (long long)gridDim.x * blockDim.x;
    for (long long i = blockIdx.x * (long long)blockDim.x + threadIdx.x; i < nw; i += stride)
        g_bmp[i] = 0ull;
}
__global__ void k_mark(const int* __restrict__ ei) {
    int e = blockIdx.x * blockDim.x + threadIdx.x;
    if (e >= EE) return;
    int s = ei[e], d = ei[EE + e];
    if (s == d) return;
    int a = g_buggy[s], b = g_buggy[d];
    if (a == b) return;
    int c = g_c;
    if (c > CMAXB) return;
    long long cw = (c + 63) >> 6;
    if (a < 0 || a >= c || b < 0 || b >= c) return;
    long long bit = (long long)a * (cw << 6) + b;
    atomicOr(&g_bmp[bit >> 6], 1ull << (bit & 63));
}
__global__ void k_rowcnt() {
    int a = blockIdx.x * blockDim.x + threadIdx.x;
    int c = g_c;
    if (a >= NN) return;
    if (a >= c || c > CMAXB) { g_rowcnt[a] = 0; return; }
    long long cw = (c + 63) >> 6;
    int cnt = 0;
    for (long long w = 0; w < cw; w++) cnt += __popcll(g_bmp[(long long)a * cw + w]);
    g_rowcnt[a] = cnt;
}

// ---------------- scan B ----------------
__global__ void k_scanB1() {
    __shared__ int sh[1024];
    int n = g_c; if (n > NN) n = NN;
    int b = blockIdx.x, tid = threadIdx.x;
    int idx = b * 1024 + tid;
    int v = (idx < n) ? g_rowcnt[idx] : 0;
    sh[tid] = v;
    __syncthreads();
    for (int d = 1; d < 1024; d <<= 1) {
        int t = (tid >= d) ? sh[tid - d] : 0;
        __syncthreads();
        sh[tid] += t;
        __syncthreads();
    }
    if (idx < n) g_rowincl[idx] = sh[tid];
    if (tid == 1023) g_aux[b] = sh[1023];
}
__global__ void k_scanB2() {
    int run = 0;
    for (int b = 0; b < 98; b++) { int t = g_aux[b]; g_aux[b] = run; run += t; }
}
__global__ void k_scanB3() {
    int n = g_c; if (n > NN) n = NN;
    int idx = blockIdx.x * 1024 + threadIdx.x;
    if (idx < n) g_rowincl[idx] += g_aux[idx >> 10];
}
__global__ void k_setE() {
    int c = g_c;
    g_Etot = (c > 0 && c <= NN) ? g_rowincl[c - 1] : 0;
}

// ---------------- x_p = segment_max ----------------
__global__ void k_xclear() {
    long long i = blockIdx.x * (long long)blockDim.x + threadIdx.x;
    if (i < (long long)NN * FD) g_enc[i] = 0u;
}
__global__ void k_xmax(const float* __restrict__ x) {
    long long i = blockIdx.x * (long long)blockDim.x + threadIdx.x;
    if (i >= (long long)NN * FD) return;
    int v = (int)(i / FD), f = (int)(i % FD);
    int cl = g_cluster[v];
    if (cl < 0 || cl >= NN) return;
    unsigned u = __float_as_uint(x[i]);
    u = (u >> 31) ? ~u : (u | 0x80000000u);
    atomicMax(&g_enc[(long long)cl * FD + f], u);
}
__global__ void k_xout(float* __restrict__ out, long long osz) {
    long long i = blockIdx.x * (long long)blockDim.x + threadIdx.x;
    if (i >= (long long)g_c * FD || i >= osz) return;
    unsigned u = g_enc[i];
    unsigned bits = (u & 0x80000000u) ? (u ^ 0x80000000u) : ~u;
    out[i] = __uint_as_float(bits);
}

// ---------------- new_ei emission ----------------
__global__ void k_emit(float* __restrict__ out, long long osz) {
    int a = blockIdx.x * blockDim.x + threadIdx.x;
    int c = g_c;
    if (a >= c || c > CMAXB) return;
    long long cw = (c + 63) >> 6;
    int base = g_rowincl[a] - g_rowcnt[a];
    long long eoff = (long long)FD * c;
    int Et = g_Etot;
    int cnt = 0;
    for (long long w = 0; w < cw; w++) {
        ull u = g_bmp[(long long)a * cw + w];
        while (u) {
            int bpos = __ffsll((long long)u) - 1;
            int b = (int)(w * 64 + bpos);
            long long p0 = eoff + base + cnt;
            long long p1 = eoff + Et + base + cnt;
            if (p0 >= 0 && p0 < osz) out[p0] = (float)a;
            if (p1 >= 0 && p1 < osz) out[p1] = (float)b;
            cnt++;
            u &= (u - 1);
        }
    }
}

// ---------------- pos_p ----------------
__global__ void k_posout(const float* __restrict__ pos, float* __restrict__ out,
                         long long osz) {
    int i = blockIdx.x * blockDim.x + threadIdx.x;
    int c = g_c;
    if (i >= 3 * c) return;
    int j = i / 3, d = i % 3;
    int ctr = g_centers[j];
    if (ctr < 0 || ctr >= NN) return;
    long long off = (long long)FD * c + 2LL * g_Etot + i;
    if (off >= 0 && off < osz)
        out[off] = pos[(long long)ctr * 3 + d];
}

// ---------------- host-side sort driver (launches only) ----------------
static void run_sort() {
    k_sort_local<<<MSEL / 2048, 1024>>>();
    for (int k2 = 4096; k2 <= MSEL; k2 <<= 1) {
        for (int j = k2 >> 1; j >= 2048; j >>= 1)
            k_bitonic<<<MSEL / 256, 256>>>(j, k2);
        k_merge_local<<<MSEL / 2048, 1024>>>(k2);
    }
}

// ---------------- launch ----------------
extern "C" void kernel_launch(void* const* d_in, const int* in_sizes, int n_in,
                              void* d_out, int out_size) {
    const float* x     = (const float*)d_in[0];
    const int*   ei    = (const int*)d_in[1];
    const float* pos   = (const float*)d_in[2];
    const float* wroot = (const float*)d_in[3];
    const float* wrel  = (const float*)d_in[4];
    const float* bb    = (const float*)d_in[5];
    float* out = (float*)d_out;
    long long osz = (long long)out_size;

    k_init<<<(NN + 255) / 256, 256>>>();
    k_dots<<<(NN + 7) / 8, 256>>>(x, pos, wroot, wrel);
    k_edge1<<<(EE + 255) / 256, 256>>>(ei);
    k_minred<<<(NN + 255) / 256, 256>>>();
    k_kcalc<<<1, 1>>>();
    k_key<<<MSEL / 256, 256>>>(bb);
    run_sort();                                   // sel order
    k_scanA1<<<98, 1024>>>();
    k_scanA2<<<1, 1>>>();
    k_scanA3<<<98, 1024>>>();
    k_fillself<<<98, 1024>>>();
    k_adjE<<<(EE + 255) / 256, 256>>>(ei);
    k_peel4<<<NBLK, 256>>>();
    k_key2<<<MSEL / 256, 256>>>();
    run_sort();                                   // concat order (cluster, node)
    k_clearbmp<<<2048, 256>>>();
    k_buggy<<<(NN + 255) / 256, 256>>>();
    k_mark<<<(EE + 255) / 256, 256>>>(ei);
    k_rowcnt<<<(NN + 255) / 256, 256>>>();
    k_scanB1<<<98, 1024>>>();
    k_scanB2<<<1, 1>>>();
    k_scanB3<<<98, 1024>>>();
    k_setE<<<1, 1>>>();
    k_xclear<<<(NN * FD + 255) / 256, 256>>>();
    k_xmax<<<(NN * FD + 255) / 256, 256>>>(x);
    k_xout<<<(NN * FD + 255) / 256, 256>>>(out, osz);
    k_emit<<<(NN + 255) / 256, 256>>>(out, osz);
    k_posout<<<(3 * NN + 255) / 256, 256>>>(pos, out, osz);
}

// round 11
// speedup vs baseline: 2.5698x; 1.3214x over previous
#include <cuda_runtime.h>
#include <math.h>
#include <stdint.h>

typedef unsigned long long ull;

// ---------------- problem constants ----------------
#define NN 100000
#define EE 1600000
#define FD 125
#define PD 3
#define MSEL 131072            // pow2 >= NN
#define NBLK 128               // persistent blocks (all wave-1 resident)
#define NT (NBLK*256)          // grid threads = 32768
#define BB 128                 // speculative batch = NBLK
#define REGC 16384             // per-slot region capacity (slots > 0)
#define BMPW (1u<<24)          // 2^24 words = 2^30 bits bitmap (c <= 32768)
#define CMAXB 32768
#define QSCALE 17179869184.0   // 2^34 fixed-point scale
#define QINV   (1.0/17179869184.0)

// ---------------- static device scratch ----------------
__device__ double  g_sroot[NN];
__device__ double  g_srel[NN];
__device__ long long g_qrel[NN];
__device__ ull     g_relfix[NN];
__device__ int     g_deg[NN];
__device__ int     g_indptr[NN + 1];
__device__ int     g_fill[NN];
__device__ int     g_adj[NN + EE];
__device__ ull     g_key[MSEL];
__device__ int     g_cluster[NN];
__device__ int     g_centers[NN];
__device__ int     g_buggy[NN];
__device__ int     g_f0[NN];           // slot-0 region list (never truncates)
__device__ int     g_reg[BB][REGC];    // per-slot region lists (slots 1..BB-1)
__device__ int     g_regsz[BB];
__device__ unsigned g_mark[NN];        // speculative marks: (epoch<<10)|(1023-slot)
__device__ int     g_cand[BB];
__device__ int     g_candpos[BB];
__device__ int     g_conf[2][BB];      // HARD flags, double-buffered by round parity
__device__ unsigned g_blkm[BB * 4];    // blocked-by bitmask (lost-at-touch), per slot
__device__ int     g_aflag[NT];
__device__ unsigned int g_enc[NN * FD];
__device__ ull     g_bmp[BMPW];        // 128MB
__device__ int     g_rowcnt[NN];
__device__ int     g_rowincl[NN];
__device__ int     g_aux[128];
__device__ int     g_selfcnt;
__device__ int     g_degmin;
__device__ int     g_depth;
__device__ int     g_c;
__device__ int     g_Etot;
// persistent-kernel coordination
__device__ int     g_epoch, g_P, g_C, g_found, g_selDone, g_scanbase;
__device__ int     g_barArrive, g_barGen;

// ---------------- init ----------------
__global__ void k_init() {
    int v = blockIdx.x * blockDim.x + threadIdx.x;
    if (v < NN) {
        g_deg[v] = 1;        // appended self-loop
        g_relfix[v] = 0ull;
        g_cluster[v] = -1;
        g_mark[v] = 0u;
    }
    if (v < BB) { g_conf[0][v] = 0; g_conf[1][v] = 0; g_regsz[v] = 0; }
    if (v < BB * 4) g_blkm[v] = 0u;
    if (v == 0) {
        g_selfcnt = 0; g_degmin = 0x7fffffff;
        g_epoch = 1; g_P = 0; g_C = 0;
        g_found = 0; g_scanbase = 0; g_selDone = 0;
        g_barArrive = 0; g_barGen = 0;
    }
}

// ---------------- per-node 128-dim dots (fp64, warp per node) ----------------
__global__ void k_dots(const float* __restrict__ x, const float* __restrict__ pos,
                       const float* __restrict__ wroot, const float* __restrict__ wrel) {
    int tid = threadIdx.x;
    int warp = tid >> 5, lane = tid & 31;
    int v = blockIdx.x * 8 + warp;
    if (v >= NN) return;
    double ar = 0.0, rr = 0.0;
    for (int d = lane; d < 128; d += 32) {
        double val = (d < FD) ? (double)x[(size_t)v * FD + d]
                              : (double)pos[(size_t)v * PD + (d - FD)];
        ar += val * (double)wroot[d];
        rr += val * (double)wrel[d];
    }
    for (int o = 16; o > 0; o >>= 1) {
        ar += __shfl_down_sync(0xffffffffu, ar, o);
        rr += __shfl_down_sync(0xffffffffu, rr, o);
    }
    if (lane == 0) {
        g_sroot[v] = ar;
        g_srel[v]  = rr;
        g_qrel[v]  = llrint(rr * QSCALE);
    }
}

// ---------------- edge pass ----------------
__global__ void k_edge1(const int* __restrict__ ei) {
    int e = blockIdx.x * blockDim.x + threadIdx.x;
    if (e >= EE) return;
    int s = ei[e], d = ei[EE + e];
    if (s == d) {
        atomicAdd(&g_selfcnt, 1);
    } else {
        atomicAdd(&g_deg[s], 1);
        atomicAdd(&g_relfix[d], (ull)g_qrel[s]);
    }
}

__global__ void k_minred() {
    int v = blockIdx.x * blockDim.x + threadIdx.x;
    if (v < NN) atomicMin(&g_degmin, g_deg[v]);
}

__global__ void k_kcalc() {
    long long kept = (long long)EE - g_selfcnt;
    double mean = (double)(kept + NN) / (double)NN;
    double b = log(mean - (double)g_degmin);
    double a = log(1.0 / 0.8);
    long long kk = (long long)ceil(a / b);
    int d = (int)kk + 2;
    if (d < 1) d = 1;
    if (d > 16) d = 16;
    g_depth = d;
}

// ---------------- score -> sortable key ----------------
__global__ void k_key(const float* __restrict__ bptr) {
    int i = blockIdx.x * blockDim.x + threadIdx.x;
    if (i >= MSEL) return;
    if (i < NN) {
        double sc = g_sroot[i] + g_srel[i] + (double)(long long)g_relfix[i] * QINV
                  + (double)bptr[0];
        float f = (float)sc;
        unsigned u = __float_as_uint(f);
        u = (u >> 31) ? ~u : (u | 0x80000000u);
        unsigned du = ~u;
        g_key[i] = ((ull)du << 32) | (unsigned)i;
    } else {
        g_key[i] = ~0ull;
    }
}

// ---------------- bitonic sort: global stage + smem-fused stages ----------------
__global__ void k_bitonic(int j, int k2) {
    int i = blockIdx.x * blockDim.x + threadIdx.x;
    int ixj = i ^ j;
    if (ixj > i) {
        ull a = g_key[i], b = g_key[ixj];
        bool up = ((i & k2) == 0);
        if ((a > b) == up) { g_key[i] = b; g_key[ixj] = a; }
    }
}

__global__ void __launch_bounds__(1024) k_sort_local() {
    __shared__ ull sh[2048];
    int base = blockIdx.x * 2048, t = threadIdx.x;
    sh[t] = g_key[base + t];
    sh[t + 1024] = g_key[base + t + 1024];
    __syncthreads();
    for (int k2 = 2; k2 <= 2048; k2 <<= 1) {
        for (int j = k2 >> 1; j > 0; j >>= 1) {
            #pragma unroll
            for (int q = 0; q < 2; q++) {
                int i = t + q * 1024;
                int ixj = i ^ j;
                if (ixj > i) {
                    bool up = (((base + i) & k2) == 0);
                    ull a = sh[i], b = sh[ixj];
                    if ((a > b) == up) { sh[i] = b; sh[ixj] = a; }
                }
            }
            __syncthreads();
        }
    }
    g_key[base + t] = sh[t];
    g_key[base + t + 1024] = sh[t + 1024];
}

__global__ void __launch_bounds__(1024) k_merge_local(int k2) {
    __shared__ ull sh[2048];
    int base = blockIdx.x * 2048, t = threadIdx.x;
    sh[t] = g_key[base + t];
    sh[t + 1024] = g_key[base + t + 1024];
    __syncthreads();
    for (int j = 1024; j > 0; j >>= 1) {
        #pragma unroll
        for (int q = 0; q < 2; q++) {
            int i = t + q * 1024;
            int ixj = i ^ j;
            if (ixj > i) {
                bool up = (((base + i) & k2) == 0);
                ull a = sh[i], b = sh[ixj];
                if ((a > b) == up) { sh[i] = b; sh[ixj] = a; }
            }
        }
        __syncthreads();
    }
    g_key[base + t] = sh[t];
    g_key[base + t + 1024] = sh[t + 1024];
}

// ---------------- scan A: deg -> indptr ----------------
__global__ void k_scanA1() {
    __shared__ int sh[1024];
    int b = blockIdx.x, tid = threadIdx.x;
    int idx = b * 1024 + tid;
    int v = (idx < NN) ? g_deg[idx] : 0;
    sh[tid] = v;
    __syncthreads();
    for (int d = 1; d < 1024; d <<= 1) {
        int t = (tid >= d) ? sh[tid - d] : 0;
        __syncthreads();
        sh[tid] += t;
        __syncthreads();
    }
    if (idx < NN) g_indptr[idx + 1] = sh[tid];
    if (tid == 1023) g_aux[b] = sh[1023];
}
__global__ void k_scanA2() {
    int run = 0;
    for (int b = 0; b < 98; b++) { int t = g_aux[b]; g_aux[b] = run; run += t; }
    g_indptr[0] = 0;
}
__global__ void k_scanA3() {
    int idx = blockIdx.x * 1024 + threadIdx.x;
    if (idx < NN) g_indptr[idx + 1] += g_aux[idx >> 10];
}

__global__ void k_fillself() {
    int v = blockIdx.x * 1024 + threadIdx.x;
    if (v < NN) {
        int p = g_indptr[v];
        g_adj[p] = v;          // self-loop at slot 0
        g_fill[v] = p + 1;
    }
}
__global__ void k_adjE(const int* __restrict__ ei) {
    int e = blockIdx.x * blockDim.x + threadIdx.x;
    if (e >= EE) return;
    int s = ei[e], d = ei[EE + e];
    if (s != d) g_adj[atomicAdd(&g_fill[s], 1)] = d;
}

// ---------------- grid barrier (all NBLK blocks resident) ----------------
__device__ __forceinline__ void gridbar(int* sgen) {
    __syncthreads();
    if (threadIdx.x == 0) {
        int g = *sgen;
        __threadfence();
        if (atomicAdd(&g_barArrive, 1) == NBLK - 1) {
            atomicExch(&g_barArrive, 0);
            __threadfence();
            atomicAdd(&g_barGen, 1);
        } else {
            while (atomicAdd(&g_barGen, 0) < g + 1) { }
        }
        __threadfence();
        *sgen = g + 1;
    }
    __syncthreads();
}

// ------- speculative peel v5: HARD/soft conflict split, inductive exactness -------
__global__ void __launch_bounds__(256) k_peel5() {
    __shared__ int s_gen, s_abort, s_hi, s_stop, s_ncommit;
    __shared__ int s_pref[256];
    __shared__ int s_ms[BB];          // decoded mark-slot of each candidate center
    __shared__ int s_hard[BB];
    __shared__ unsigned s_B[BB * 4];  // blocked-by masks
    __shared__ int s_cls[BB];         // 1=commit, 0=dead-skip (below stop)
    __shared__ int s_rank[BB];
    int tid = threadIdx.x;
    int blk = blockIdx.x;
    if (tid == 0) s_gen = g_barGen;
    __syncthreads();
    int depth = g_depth;

    for (int round = 0; round < NN; round++) {
        int par = round & 1;
        // clear own HARD flag (other parity, used next round) and own B mask
        if (tid == 0) g_conf[par ^ 1][blk] = 0;
        if (tid < 4) g_blkm[blk * 4 + tid] = 0u;

        // ---- candidate selection: first BB alive in sel order from g_P ----
        while (true) {
            int scanb = g_scanbase;
            int tg = blk * 256 + tid;
            int pos = scanb + tg;
            int fl = 0;
            if (pos < NN) {
                int s = (int)(g_key[pos] & 0xffffffffu);
                if (g_cluster[s] == -1) fl = 1;
            }
            g_aflag[tg] = fl;
            gridbar(&s_gen);                                   // bar 1
            if (blk == 0) {
                int found0 = g_found;
                int need = BB - found0;
                const int FPT = NT / 256;                      // 128 flags/thread
                int base = tid * FPT;
                int cnt = 0;
                for (int k2 = 0; k2 < FPT; k2++) cnt += g_aflag[base + k2];
                s_pref[tid] = cnt;
                __syncthreads();
                for (int d = 1; d < 256; d <<= 1) {
                    int v = (tid >= d) ? s_pref[tid - d] : 0;
                    __syncthreads();
                    s_pref[tid] += v;
                    __syncthreads();
                }
                int excl = s_pref[tid] - cnt;
                int total = s_pref[255];
                int r = excl;
                for (int k2 = 0; k2 < FPT; k2++) {
                    if (g_aflag[base + k2]) {
                        if (r < need) {
                            int p2 = scanb + base + k2;
                            g_cand[found0 + r] = (int)(g_key[p2] & 0xffffffffu);
                            g_candpos[found0 + r] = p2;
                        }
                        r++;
                    }
                }
                __syncthreads();
                if (tid == 0) {
                    int add = total < need ? total : need;
                    int nf = found0 + add;
                    int nsb = scanb + NT;
                    g_found = nf;
                    g_scanbase = nsb;
                    g_selDone = (nf >= BB || nsb >= NN) ? 1 : 0;
                }
            }
            gridbar(&s_gen);                                   // bar 2
            if (g_selDone) break;
        }

        int found = g_found;
        int epoch = g_epoch;
        if (found == 0) break;

        // ---- speculative BFS: one block per slot ----
        if (blk < found) {
            int slot = blk;
            int* reg = (slot == 0) ? g_f0 : g_reg[slot];
            int cap  = (slot == 0) ? NN : REGC;
            int center = g_cand[slot];
            unsigned mykey = ((unsigned)epoch << 10) | (unsigned)(1023 - slot);
            if (tid == 0) {
                s_abort = 0; s_hi = 0;
                unsigned old = atomicMax(&g_mark[center], mykey);
                if ((old >> 10) == (unsigned)epoch) {
                    int os = 1023 - (int)(old & 1023u);
                    if (os < slot) {
                        // center blocked: record soft dependency; empty region
                        atomicOr(&g_blkm[slot * 4 + (os >> 5)], 1u << (os & 31));
                        s_abort = 1;
                    } else if (os > slot) {
                        // stole center from bigger slot -> HARD on victim
                        atomicExch(&g_conf[par][os], 1);
                    }
                }
                if (!s_abort) { reg[0] = center; s_hi = 1; }
            }
            __syncthreads();
            int lo = 0;
            for (int lev = 0; lev < depth; lev++) {
                if (s_abort) break;
                int hi = s_hi;
                if (hi == lo) break;
                // self-HARD check: a smaller slot stole from us -> region invalid
                if (tid == 0 && atomicAdd(&g_conf[par][slot], 0)) s_abort = 1;
                __syncthreads();
                if (s_abort) break;
                for (int i = lo + tid; i < hi; i += 256) {
                    int u = reg[i];
                    int e0 = g_indptr[u] + 1, e1 = g_indptr[u + 1];  // skip self slot
                    for (int e = e0; e < e1; e++) {
                        int w = g_adj[e];
                        if (g_cluster[w] != -1) continue;
                        unsigned old = atomicMax(&g_mark[w], mykey);
                        bool own;
                        if ((old >> 10) != (unsigned)epoch) own = true;
                        else {
                            int os = 1023 - (int)(old & 1023u);
                            if (os == slot) continue;
                            if (os < slot) {
                                // lost at touch: soft block, keep going
                                atomicOr(&g_blkm[slot * 4 + (os >> 5)], 1u << (os & 31));
                                continue;
                            }
                            // steal from bigger slot -> HARD on victim
                            atomicExch(&g_conf[par][os], 1); own = true;
                        }
                        if (own) {
                            int j = atomicAdd(&s_hi, 1);
                            if (j < cap) reg[j] = w;
                            else { atomicExch(&g_conf[par][slot], 1); s_abort = 1; }
                        }
                    }
                }
                __syncthreads();
                lo = hi;
            }
            if (tid == 0) g_regsz[slot] = s_hi < cap ? s_hi : cap;
        }
        gridbar(&s_gen);                                       // bar 3

        // ---- commit analysis (redundant per block): prefetch, then serial walk ----
        for (int s = tid; s < found; s += 256) {
            unsigned m = g_mark[g_cand[s]];
            int ms = -1;
            if ((m >> 10) == (unsigned)epoch) ms = 1023 - (int)(m & 1023u);
            s_ms[s] = ms;
            s_hard[s] = g_conf[par][s];
        }
        for (int i = tid; i < found * 4; i += 256) s_B[i] = g_blkm[i];
        __syncthreads();
        if (tid == 0) {
            unsigned ex0 = 0, ex1 = 0, ex2 = 0, ex3 = 0;
            int stop = found, r = 0;
            for (int s = 0; s < found; s++) {
                int ms = s_ms[s];
                bool ok = false;
                if (ms == s && !s_hard[s]) {
                    ok = ((s_B[4*s+0] & ~ex0) == 0) && ((s_B[4*s+1] & ~ex1) == 0)
                      && ((s_B[4*s+2] & ~ex2) == 0) && ((s_B[4*s+3] & ~ex3) == 0);
                }
                if (ok) {
                    s_cls[s] = 1; s_rank[s] = r; r++;
                    if      (s < 32)  ex0 |= 1u << s;
                    else if (s < 64)  ex1 |= 1u << (s - 32);
                    else if (s < 96)  ex2 |= 1u << (s - 64);
                    else              ex3 |= 1u << (s - 96);
                } else if (ms >= 0 && ms < s &&
                           (((ms < 32 ? ex0 : ms < 64 ? ex1 : ms < 96 ? ex2 : ex3)
                             >> (ms & 31)) & 1u)) {
                    s_cls[s] = 0;                 // dead: center inside exact region
                } else {
                    stop = s; break;              // unknown -> stop
                }
            }
            s_stop = stop; s_ncommit = r;
        }
        __syncthreads();
        int stop = s_stop;                        // >= 1 (slot 0 always exact)
        int C = g_C;

        // committed slots write their regions with re-ranked ids
        if (blk < stop && s_cls[blk] == 1) {
            int* reg = (blk == 0) ? g_f0 : g_reg[blk];
            int sz = g_regsz[blk];
            int cid = C + s_rank[blk];
            for (int i = tid; i < sz; i += 256) g_cluster[reg[i]] = cid;
        }
        if (blk == 0) {
            for (int s = tid; s < stop; s += 256)
                if (s_cls[s] == 1) g_centers[C + s_rank[s]] = g_cand[s];
            if (tid == 0) {
                g_C = C + s_ncommit;
                int np = g_candpos[stop - 1] + 1;
                g_P = np;
                g_epoch = epoch + 1;
                g_found = 0; g_scanbase = np; g_selDone = 0;
            }
        }
        gridbar(&s_gen);                                       // bar 4
    }
    if (blk == 0 && tid == 0) g_c = g_C;
}

// ---------------- concat reconstruction: key = (cluster<<32 | node) ----------------
__global__ void k_key2() {
    int i = blockIdx.x * blockDim.x + threadIdx.x;
    if (i >= MSEL) return;
    if (i < NN) {
        int cl = g_cluster[i];
        unsigned uc = (cl < 0) ? 0x7fffffffu : (unsigned)cl;
        g_key[i] = ((ull)uc << 32) | (unsigned)i;
    } else {
        g_key[i] = ~0ull;
    }
}

// After sort: position p holds key[p] = (cid[p]<<32 | oid[p]).
// Reference: clusters_buggy[v] = cid[ oid[v] ]  (cluster-id AT POSITION oid[v]).
__global__ void k_buggy() {
    int v = blockIdx.x * blockDim.x + threadIdx.x;
    if (v >= NN) return;
    int p = (int)(g_key[v] & 0xffffffffu);   // oid[v]
    int cid = 0;
    if (p >= 0 && p < NN) cid = (int)(g_key[p] >> 32);
    g_buggy[v] = cid;
}

// ---------------- edge dedup bitmap ----------------
__global__ void k_clearbmp() {
    int c = g_c; if (c > CMAXB) c = CMAXB;
    long long cw = (c + 63) >> 6;
    long long nw = (long long)c * cw;
    if (nw > (long long)BMPW) nw = BMPW;
    long long stride = (long long)gridDim.x * blockDim.x;
    for (long long i = blockIdx.x * (long long)blockDim.x + threadIdx.x; i < nw; i += stride)
        g_bmp[i] = 0ull;
}
__global__ void k_mark(const int* __restrict__ ei) {
    int e = blockIdx.x * blockDim.x + threadIdx.x;
    if (e >= EE) return;
    int s = ei[e], d = ei[EE + e];
    if (s == d) return;
    int a = g_buggy[s], b = g_buggy[d];
    if (a == b) return;
    int c = g_c;
    if (c > CMAXB) return;
    long long cw = (c + 63) >> 6;
    if (a < 0 || a >= c || b < 0 || b >= c) return;
    long long bit = (long long)a * (cw << 6) + b;
    atomicOr(&g_bmp[bit >> 6], 1ull << (bit & 63));
}
__global__ void k_rowcnt() {
    int a = blockIdx.x * blockDim.x + threadIdx.x;
    int c = g_c;
    if (a >= NN) return;
    if (a >= c || c > CMAXB) { g_rowcnt[a] = 0; return; }
    long long cw = (c + 63) >> 6;
    int cnt = 0;
    for (long long w = 0; w < cw; w++) cnt += __popcll(g_bmp[(long long)a * cw + w]);
    g_rowcnt[a] = cnt;
}

// ---------------- scan B ----------------
__global__ void k_scanB1() {
    __shared__ int sh[1024];
    int n = g_c; if (n > NN) n = NN;
    int b = blockIdx.x, tid = threadIdx.x;
    int idx = b * 1024 + tid;
    int v = (idx < n) ? g_rowcnt[idx] : 0;
    sh[tid] = v;
    __syncthreads();
    for (int d = 1; d < 1024; d <<= 1) {
        int t = (tid >= d) ? sh[tid - d] : 0;
        __syncthreads();
        sh[tid] += t;
        __syncthreads();
    }
    if (idx < n) g_rowincl[idx] = sh[tid];
    if (tid == 1023) g_aux[b] = sh[1023];
}
__global__ void k_scanB2() {
    int run = 0;
    for (int b = 0; b < 98; b++) { int t = g_aux[b]; g_aux[b] = run; run += t; }
}
__global__ void k_scanB3() {
    int n = g_c; if (n > NN) n = NN;
    int idx = blockIdx.x * 1024 + threadIdx.x;
    if (idx < n) g_rowincl[idx] += g_aux[idx >> 10];
}
__global__ void k_setE() {
    int c = g_c;
    g_Etot = (c > 0 && c <= NN) ? g_rowincl[c - 1] : 0;
}

// ---------------- x_p = segment_max ----------------
__global__ void k_xclear() {
    long long i = blockIdx.x * (long long)blockDim.x + threadIdx.x;
    if (i < (long long)NN * FD) g_enc[i] = 0u;
}
__global__ void k_xmax(const float* __restrict__ x) {
    long long i = blockIdx.x * (long long)blockDim.x + threadIdx.x;
    if (i >= (long long)NN * FD) return;
    int v = (int)(i / FD), f = (int)(i % FD);
    int cl = g_cluster[v];
    if (cl < 0 || cl >= NN) return;
    unsigned u = __float_as_uint(x[i]);
    u = (u >> 31) ? ~u : (u | 0x80000000u);
    atomicMax(&g_enc[(long long)cl * FD + f], u);
}
__global__ void k_xout(float* __restrict__ out, long long osz) {
    long long i = blockIdx.x * (long long)blockDim.x + threadIdx.x;
    if (i >= (long long)g_c * FD || i >= osz) return;
    unsigned u = g_enc[i];
    unsigned bits = (u & 0x80000000u) ? (u ^ 0x80000000u) : ~u;
    out[i] = __uint_as_float(bits);
}

// ---------------- new_ei emission ----------------
__global__ void k_emit(float* __restrict__ out, long long osz) {
    int a = blockIdx.x * blockDim.x + threadIdx.x;
    int c = g_c;
    if (a >= c || c > CMAXB) return;
    long long cw = (c + 63) >> 6;
    int base = g_rowincl[a] - g_rowcnt[a];
    long long eoff = (long long)FD * c;
    int Et = g_Etot;
    int cnt = 0;
    for (long long w = 0; w < cw; w++) {
        ull u = g_bmp[(long long)a * cw + w];
        while (u) {
            int bpos = __ffsll((long long)u) - 1;
            int b = (int)(w * 64 + bpos);
            long long p0 = eoff + base + cnt;
            long long p1 = eoff + Et + base + cnt;
            if (p0 >= 0 && p0 < osz) out[p0] = (float)a;
            if (p1 >= 0 && p1 < osz) out[p1] = (float)b;
            cnt++;
            u &= (u - 1);
        }
    }
}

// ---------------- pos_p ----------------
__global__ void k_posout(const float* __restrict__ pos, float* __restrict__ out,
                         long long osz) {
    int i = blockIdx.x * blockDim.x + threadIdx.x;
    int c = g_c;
    if (i >= 3 * c) return;
    int j = i / 3, d = i % 3;
    int ctr = g_centers[j];
    if (ctr < 0 || ctr >= NN) return;
    long long off = (long long)FD * c + 2LL * g_Etot + i;
    if (off >= 0 && off < osz)
        out[off] = pos[(long long)ctr * 3 + d];
}

// ---------------- host-side sort driver (launches only) ----------------
static void run_sort() {
    k_sort_local<<<MSEL / 2048, 1024>>>();
    for (int k2 = 4096; k2 <= MSEL; k2 <<= 1) {
        for (int j = k2 >> 1; j >= 2048; j >>= 1)
            k_bitonic<<<MSEL / 256, 256>>>(j, k2);
        k_merge_local<<<MSEL / 2048, 1024>>>(k2);
    }
}

// ---------------- launch ----------------
extern "C" void kernel_launch(void* const* d_in, const int* in_sizes, int n_in,
                              void* d_out, int out_size) {
    const float* x     = (const float*)d_in[0];
    const int*   ei    = (const int*)d_in[1];
    const float* pos   = (const float*)d_in[2];
    const float* wroot = (const float*)d_in[3];
    const float* wrel  = (const float*)d_in[4];
    const float* bb    = (const float*)d_in[5];
    float* out = (float*)d_out;
    long long osz = (long long)out_size;

    k_init<<<(NN + 255) / 256, 256>>>();
    k_dots<<<(NN + 7) / 8, 256>>>(x, pos, wroot, wrel);
    k_edge1<<<(EE + 255) / 256, 256>>>(ei);
    k_minred<<<(NN + 255) / 256, 256>>>();
    k_kcalc<<<1, 1>>>();
    k_key<<<MSEL / 256, 256>>>(bb);
    run_sort();                                   // sel order
    k_scanA1<<<98, 1024>>>();
    k_scanA2<<<1, 1>>>();
    k_scanA3<<<98, 1024>>>();
    k_fillself<<<98, 1024>>>();
    k_adjE<<<(EE + 255) / 256, 256>>>(ei);
    k_peel5<<<NBLK, 256>>>();
    k_key2<<<MSEL / 256, 256>>>();
    run_sort();                                   // concat order (cluster, node)
    k_clearbmp<<<2048, 256>>>();
    k_buggy<<<(NN + 255) / 256, 256>>>();
    k_mark<<<(EE + 255) / 256, 256>>>(ei);
    k_rowcnt<<<(NN + 255) / 256, 256>>>();
    k_scanB1<<<98, 1024>>>();
    k_scanB2<<<1, 1>>>();
    k_scanB3<<<98, 1024>>>();
    k_setE<<<1, 1>>>();
    k_xclear<<<(NN * FD + 255) / 256, 256>>>();
    k_xmax<<<(NN * FD + 255) / 256, 256>>>(x);
    k_xout<<<(NN * FD + 255) / 256, 256>>>(out, osz);
    k_emit<<<(NN + 255) / 256, 256>>>(out, osz);
    k_posout<<<(3 * NN + 255) / 256, 256>>>(pos, out, osz);
}